// round 14
// baseline (speedup 1.0000x reference)
#include <cuda_runtime.h>
#include <cuda_bf16.h>
#include <cuda_fp16.h>
#include <math.h>
#include <stdint.h>

#define Bb 2
#define Nn 1024
#define Dd 512
#define Hh 8
#define HD 64
#define FFN 2048
#define SPL 2
#define NSPLIT (Nn / SPL)
#define TJA 128

// ---------------- scratch ----------------
__device__ float g_wo [Bb*Nn*Dd];
__device__ float g_x1 [Bb*Nn*Dd];
__device__ float g_f2 [Bb*Nn*Dd];
__device__ float g_pacc[SPL*Bb*Nn*Dd];
__device__ float g_pm[SPL*Bb*Nn*Hh];
__device__ float g_pl[SPL*Bb*Nn*Hh];
__device__ float g_bqkv[3*Dd];

__device__ __half g_x16 [Bb*Nn*Dd];
__device__ __half g_q16 [Bb*Nn*Dd];          // scaled by 1/8
__device__ __half g_k16 [Bb*Nn*Dd];
__device__ __half g_v16 [Bb*Nn*Dd];          // row-major
__device__ __half g_vt16[Bb*Dd*Nn];          // transposed [b,ch,tok]
__device__ __half g_ao16[Bb*Nn*Dd];
__device__ __half g_x116[Bb*Nn*Dd];
__device__ __half g_h16 [Bb*Nn*FFN];
__device__ __half g_rpe[Bb*Hh*Nn*Nn];
__device__ __half g_wqkvt16[3*Dd*Dd];
__device__ __half g_woth16[Dd*Dd];
__device__ __half g_f1th16[Dd*FFN];
__device__ __half g_f2th16[FFN*Dd];

struct SideStream {
    cudaStream_t s = nullptr;
    cudaEvent_t fork = nullptr, join = nullptr;
    SideStream() {
        cudaStreamCreateWithFlags(&s, cudaStreamNonBlocking);
        cudaEventCreateWithFlags(&fork, cudaEventDisableTiming);
        cudaEventCreateWithFlags(&join, cudaEventDisableTiming);
    }
};
static SideStream g_ss;

__device__ __forceinline__ float gelu_exact(float x) {
    return 0.5f * x * (1.0f + erff(x * 0.70710678118654752f));
}
__device__ __forceinline__ uint32_t packh2(float a, float b) {
    __half2 h = __floats2half2_rn(a, b);
    return *(uint32_t*)&h;
}
__device__ __forceinline__ uint32_t f2tf(float f) {
    uint32_t r;
    asm("cvt.rna.tf32.f32 %0, %1;" : "=r"(r) : "f"(f));
    return r;
}
__device__ __forceinline__ uint32_t smem_u32(const void* p) {
    uint32_t a;
    asm("{ .reg .u64 t; cvta.to.shared.u64 t, %1; cvt.u32.u64 %0, t; }" : "=r"(a) : "l"(p));
    return a;
}
__device__ __forceinline__ void cp16(uint32_t saddr, const void* g) {
    asm volatile("cp.async.ca.shared.global [%0], [%1], 16;" :: "r"(saddr), "l"(g));
}
__device__ __forceinline__ void cp_commit() { asm volatile("cp.async.commit_group;" ::: "memory"); }
__device__ __forceinline__ void cp_wait0()  { asm volatile("cp.async.wait_group 0;" ::: "memory"); }

__device__ __forceinline__ void mma16816h(float* c, const uint32_t* a, const uint32_t* b) {
    asm volatile("mma.sync.aligned.m16n8k16.row.col.f32.f16.f16.f32 "
        "{%0,%1,%2,%3}, {%4,%5,%6,%7}, {%8,%9}, {%0,%1,%2,%3};"
        : "+f"(c[0]), "+f"(c[1]), "+f"(c[2]), "+f"(c[3])
        : "r"(a[0]), "r"(a[1]), "r"(a[2]), "r"(a[3]), "r"(b[0]), "r"(b[1]));
}
__device__ __forceinline__ void mma1688tf(float* c, const uint32_t* a, const uint32_t* b) {
    asm volatile("mma.sync.aligned.m16n8k8.row.col.f32.tf32.tf32.f32 "
        "{%0,%1,%2,%3}, {%4,%5,%6,%7}, {%8,%9}, {%0,%1,%2,%3};"
        : "+f"(c[0]), "+f"(c[1]), "+f"(c[2]), "+f"(c[3])
        : "r"(a[0]), "r"(a[1]), "r"(a[2]), "r"(a[3]), "r"(b[0]), "r"(b[1]));
}

// ============ fp16 1-term GEMM ============
// EPI: 0 = fp32 row-major; 2 = GELU -> fp16; 3 = QKV routing (q scaled 1/8, k, v fp16).
template<int BN, int EPI>
__global__ __launch_bounds__(256)
void gemm_f16_kernel(const __half* __restrict__ Af,
                     const __half* __restrict__ Bf,
                     const float* __restrict__ bias,
                     float* __restrict__ outF, __half* __restrict__ outH,
                     __half* __restrict__ outK, __half* __restrict__ outV,
                     int M, int K, int Nc)
{
    constexpr int BM = 128;
    constexpr int WM = (BN == 128) ? 2 : 4;
    constexpr int WN = 8 / WM;
    constexpr int WTM = BM / WM;
    constexpr int WTN = BN / WN;
    constexpr int MT = WTM / 16;
    constexpr int NT = WTN / 8;
    constexpr int AS = 40;

    extern __shared__ __half smh[];
    __half* sAbase = smh;
    __half* sBbase = smh + 2 * BM * AS;

    const int t = threadIdx.x;
    const int wid = t >> 5, lane = t & 31;
    const int gid = lane >> 2, tig = lane & 3;
    const int wm = wid % WM, wn = wid / WM;
    const int mtile = blockIdx.y * BM, ntile = blockIdx.x * BN;

    float acc[MT][NT][4];
    #pragma unroll
    for (int i = 0; i < MT; i++)
        #pragma unroll
        for (int j = 0; j < NT; j++)
            #pragma unroll
            for (int r = 0; r < 4; r++) acc[i][j][r] = 0.0f;

    const int lr = t >> 2;
    const int lc = (t & 3) << 3;
    const int nch = K >> 5;

    auto load_stage = [&](int st, int k0) {
        __half* sA = sAbase + st * BM * AS;
        __half* sB = sBbase + st * BN * AS;
        #pragma unroll
        for (int rep = 0; rep < BM / 64; rep++) {
            const int rr = lr + rep * 64;
            cp16(smem_u32(sA + rr * AS + lc), Af + (size_t)(mtile + rr) * K + k0 + lc);
        }
        #pragma unroll
        for (int rep = 0; rep < BN / 64; rep++) {
            const int rr = lr + rep * 64;
            cp16(smem_u32(sB + rr * AS + lc), Bf + (size_t)(ntile + rr) * K + k0 + lc);
        }
        cp_commit();
    };

    load_stage(0, 0);

    for (int c = 0; c < nch; c++) {
        cp_wait0();
        __syncthreads();
        if (c + 1 < nch) load_stage((c + 1) & 1, (c + 1) << 5);

        const int st = c & 1;
        const __half* sA = sAbase + st * BM * AS;
        const __half* sB = sBbase + st * BN * AS;

        #pragma unroll
        for (int kk = 0; kk < 2; kk++) {
            const int kb = kk * 16 + 2 * tig;
            uint32_t af[MT][4], bf[NT][2];
            #pragma unroll
            for (int i = 0; i < MT; i++) {
                const int row = wm * WTM + i * 16 + gid;
                const __half* p = sA + row * AS + kb;
                af[i][0] = *(const uint32_t*)p;
                af[i][1] = *(const uint32_t*)(p + 8 * AS);
                af[i][2] = *(const uint32_t*)(p + 8);
                af[i][3] = *(const uint32_t*)(p + 8 * AS + 8);
            }
            #pragma unroll
            for (int j = 0; j < NT; j++) {
                const int nrow = wn * WTN + j * 8 + gid;
                const __half* p = sB + nrow * AS + kb;
                bf[j][0] = *(const uint32_t*)p;
                bf[j][1] = *(const uint32_t*)(p + 8);
            }
            #pragma unroll
            for (int i = 0; i < MT; i++)
                #pragma unroll
                for (int j = 0; j < NT; j++)
                    mma16816h(acc[i][j], af[i], bf[j]);
        }
        __syncthreads();
    }

    #pragma unroll
    for (int i = 0; i < MT; i++) {
        const int r0 = mtile + wm * WTM + i * 16 + gid;
        const int r1 = r0 + 8;
        #pragma unroll
        for (int j = 0; j < NT; j++) {
            const int n = ntile + wn * WTN + j * 8 + 2 * tig;
            const float b0 = bias[n], b1 = bias[n + 1];
            float v00 = acc[i][j][0] + b0, v01 = acc[i][j][1] + b1;
            float v10 = acc[i][j][2] + b0, v11 = acc[i][j][3] + b1;
            if (EPI == 0) {
                *(float2*)&outF[(size_t)r0 * Nc + n] = make_float2(v00, v01);
                *(float2*)&outF[(size_t)r1 * Nc + n] = make_float2(v10, v11);
            } else if (EPI == 2) {
                __half2 o0 = __floats2half2_rn(gelu_exact(v00), gelu_exact(v01));
                __half2 o1 = __floats2half2_rn(gelu_exact(v10), gelu_exact(v11));
                *(__half2*)&outH[(size_t)r0 * Nc + n] = o0;
                *(__half2*)&outH[(size_t)r1 * Nc + n] = o1;
            } else { // EPI 3: QKV routing
                if (n < Dd) {
                    *(uint32_t*)&outH[(size_t)r0 * Dd + n] = packh2(v00 * 0.125f, v01 * 0.125f);
                    *(uint32_t*)&outH[(size_t)r1 * Dd + n] = packh2(v10 * 0.125f, v11 * 0.125f);
                } else if (n < 2 * Dd) {
                    const int ch = n - Dd;
                    *(uint32_t*)&outK[(size_t)r0 * Dd + ch] = packh2(v00, v01);
                    *(uint32_t*)&outK[(size_t)r1 * Dd + ch] = packh2(v10, v11);
                } else {
                    const int ch = n - 2 * Dd;
                    *(uint32_t*)&outV[(size_t)r0 * Dd + ch] = packh2(v00, v01);
                    *(uint32_t*)&outV[(size_t)r1 * Dd + ch] = packh2(v10, v11);
                }
            }
        }
    }
}

// ============ weight prep: fp32 [K,Nc] -> fp16 [Nc,K] ============
__global__ void transpose_f16_kernel(const float* __restrict__ W,
                                     __half* __restrict__ T,
                                     int K, int Nc)
{
    __shared__ float tile[32][33];
    const int n0 = blockIdx.x * 32, k0 = blockIdx.y * 32;
    const int tx = threadIdx.x, ty = threadIdx.y;
    #pragma unroll
    for (int dy = 0; dy < 32; dy += 8)
        tile[ty + dy][tx] = W[(size_t)(k0 + ty + dy) * Nc + n0 + tx];
    __syncthreads();
    #pragma unroll
    for (int dy = 0; dy < 32; dy += 8) {
        const size_t o = (size_t)(n0 + ty + dy) * K + k0 + tx;
        T[o] = __float2half_rn(tile[tx][ty + dy]);
    }
}

// QKV weight transpose + bias concat
__global__ void transpose_f16_qkv_kernel(const float* __restrict__ Wq,
                                         const float* __restrict__ Wk,
                                         const float* __restrict__ Wv,
                                         const float* __restrict__ bq,
                                         const float* __restrict__ bk,
                                         const float* __restrict__ bv,
                                         __half* __restrict__ T,
                                         float* __restrict__ bqkv)
{
    __shared__ float tile[32][33];
    const int z = blockIdx.z;
    const float* W = (z == 0) ? Wq : (z == 1) ? Wk : Wv;
    const size_t woff = (size_t)z * Dd * Dd;
    const int n0 = blockIdx.x * 32, k0 = blockIdx.y * 32;
    const int tx = threadIdx.x, ty = threadIdx.y;
    if (blockIdx.y == 0 && ty == 0) {
        const float* bsrc = (z == 0) ? bq : (z == 1) ? bk : bv;
        bqkv[z * Dd + n0 + tx] = bsrc[n0 + tx];
    }
    #pragma unroll
    for (int dy = 0; dy < 32; dy += 8)
        tile[ty + dy][tx] = W[(size_t)(k0 + ty + dy) * Dd + n0 + tx];
    __syncthreads();
    #pragma unroll
    for (int dy = 0; dy < 32; dy += 8) {
        const size_t o = woff + (size_t)(n0 + ty + dy) * Dd + k0 + tx;
        T[o] = __float2half_rn(tile[tx][ty + dy]);
    }
}

// ============ fp32 -> fp16 elementwise ============
__global__ void to_f16_kernel(const float* __restrict__ in, __half* __restrict__ out)
{
    const int i = blockIdx.x * 256 + threadIdx.x;
    float4 v = ((const float4*)in)[i];
    ((uint32_t*)out)[i * 2 + 0] = packh2(v.x, v.y);
    ((uint32_t*)out)[i * 2 + 1] = packh2(v.z, v.w);
}

// ============ V fp16 row-major -> V^T fp16 [b,ch,tok] ============
__global__ void vT16_kernel(const __half* __restrict__ v16,
                            __half* __restrict__ vt16)
{
    __shared__ __half tile[32][40];
    const int tok0 = blockIdx.x * 32, ch0 = blockIdx.y * 32, b = blockIdx.z;
    const int tx = threadIdx.x, ty = threadIdx.y;
    #pragma unroll
    for (int dy = 0; dy < 32; dy += 8)
        tile[ty + dy][tx] = v16[((size_t)(b * Nn + tok0 + ty + dy)) * Dd + ch0 + tx];
    __syncthreads();
    #pragma unroll
    for (int dy = 0; dy < 32; dy += 8) {
        const size_t o = ((size_t)(b * Dd + ch0 + ty + dy)) * Nn + tok0 + tx;
        vt16[o] = tile[tx][ty + dy];
    }
}

// ============ RPE: tf32 layer1 -> relu -> fp16 layer2 (tensor) ============
__global__ __launch_bounds__(256)
void rpe_kernel(const float* __restrict__ rel_pos,
                const float* __restrict__ R1, const float* __restrict__ rb1,
                const float* __restrict__ R2, const float* __restrict__ rb2,
                __half* __restrict__ rpe)
{
    __shared__ __half sh_out[8][128];

    const int j0 = blockIdx.x * 128;
    const int i  = blockIdx.y;
    const int b  = blockIdx.z;
    const int t  = threadIdx.x;
    const int w = t >> 5, lane = t & 31;
    const int gid = lane >> 2, tig = lane & 3;
    const int jw = w * 16;

    uint32_t b1f[8];
    #pragma unroll
    for (int ut = 0; ut < 8; ut++) b1f[ut] = f2tf(R1[tig * 64 + ut * 8 + gid]);

    const float* rp = rel_pos + ((size_t)(b * Nn + i) * Nn + j0 + jw) * 4;
    uint32_t a1f[4];
    a1f[0] = f2tf(rp[gid * 4 + tig]);
    a1f[1] = f2tf(rp[(gid + 8) * 4 + tig]);
    a1f[2] = 0u;
    a1f[3] = 0u;

    float c1[8][4];
    #pragma unroll
    for (int ut = 0; ut < 8; ut++) {
        c1[ut][0] = 0.f; c1[ut][1] = 0.f; c1[ut][2] = 0.f; c1[ut][3] = 0.f;
        uint32_t bb[2] = { b1f[ut], 0u };
        mma1688tf(c1[ut], a1f, bb);
        const float r0 = rb1[ut * 8 + 2 * tig], r1 = rb1[ut * 8 + 2 * tig + 1];
        c1[ut][0] = fmaxf(c1[ut][0] + r0, 0.f);
        c1[ut][1] = fmaxf(c1[ut][1] + r1, 0.f);
        c1[ut][2] = fmaxf(c1[ut][2] + r0, 0.f);
        c1[ut][3] = fmaxf(c1[ut][3] + r1, 0.f);
    }

    float c2[4] = {0.f, 0.f, 0.f, 0.f};
    #pragma unroll
    for (int ks = 0; ks < 4; ks++) {
        uint32_t a2[4];
        a2[0] = packh2(c1[2 * ks][0],     c1[2 * ks][1]);
        a2[1] = packh2(c1[2 * ks][2],     c1[2 * ks][3]);
        a2[2] = packh2(c1[2 * ks + 1][0], c1[2 * ks + 1][1]);
        a2[3] = packh2(c1[2 * ks + 1][2], c1[2 * ks + 1][3]);
        uint32_t b2[2];
        b2[0] = packh2(R2[(16 * ks + 2 * tig) * 8 + gid],     R2[(16 * ks + 2 * tig + 1) * 8 + gid]);
        b2[1] = packh2(R2[(16 * ks + 8 + 2 * tig) * 8 + gid], R2[(16 * ks + 9 + 2 * tig) * 8 + gid]);
        mma16816h(c2, a2, b2);
    }
    const float rbA = rb2[2 * tig], rbB = rb2[2 * tig + 1];
    sh_out[2 * tig    ][jw + gid]     = __float2half(c2[0] + rbA);
    sh_out[2 * tig + 1][jw + gid]     = __float2half(c2[1] + rbB);
    sh_out[2 * tig    ][jw + gid + 8] = __float2half(c2[2] + rbA);
    sh_out[2 * tig + 1][jw + gid + 8] = __float2half(c2[3] + rbB);
    __syncthreads();

    const uint32_t* src = (const uint32_t*)sh_out;
    #pragma unroll
    for (int u = t; u < 512; u += 256) {
        const int hh = u >> 6, col = u & 63;
        ((uint32_t*)(rpe + (((size_t)(b * Hh + hh) * Nn + i) * Nn + j0)))[col] = src[hh * 64 + col];
    }
}

// ============ attention: TJ=128 tiles, QK/AV fp16, cp.async double-buffered ============
__global__ __launch_bounds__(128)
void attn_mma_kernel(const __half* __restrict__ q16,
                     const __half* __restrict__ k16,
                     const __half* __restrict__ vt16,
                     const __half* __restrict__ rpe,
                     float* __restrict__ pacc, float* __restrict__ pm, float* __restrict__ pl)
{
    // dynamic smem: sK[2][128*72] + sV[2][64*136]
    extern __shared__ __half dynsm[];
    __half* sKb = dynsm;                       // 2 * 9216
    __half* sVb = dynsm + 2 * 128 * 72;        // 2 * 8704

    const int it = blockIdx.x;
    const int b  = blockIdx.y;
    const int h  = blockIdx.z >> 1;
    const int sp = blockIdx.z & 1;
    const int t = threadIdx.x;
    const int w = t >> 5, lane = t & 31;
    const int gid = lane >> 2, tig = lane & 3;
    const int i0 = it * 64 + w * 16;
    const int jbeg = sp * NSPLIT;
    const int njt = NSPLIT / TJA;

    // preload q A-frags (fp16) for this warp's 16 rows
    uint32_t aq[4][4];
    {
        const __half* qb = q16 + (size_t)(b * Nn) * Dd + h * 64;
        #pragma unroll
        for (int ks = 0; ks < 4; ks++) {
            const int kb = ks * 16 + 2 * tig;
            const __half* p0 = qb + (size_t)(i0 + gid) * Dd + kb;
            const __half* p1 = qb + (size_t)(i0 + gid + 8) * Dd + kb;
            aq[ks][0] = *(const uint32_t*)p0;
            aq[ks][1] = *(const uint32_t*)p1;
            aq[ks][2] = *(const uint32_t*)(p0 + 8);
            aq[ks][3] = *(const uint32_t*)(p1 + 8);
        }
    }

    float acc[8][4];
    #pragma unroll
    for (int nf = 0; nf < 8; nf++)
        #pragma unroll
        for (int r = 0; r < 4; r++) acc[nf][r] = 0.0f;
    float m0 = -1e30f, m1 = -1e30f, l0 = 0.0f, l1 = 0.0f;

    // stage K [128 j x 64 ch] and V^T [64 ch x 128 tok]
    auto stage_tile = [&](int st, int j0) {
        __half* sK = sKb + st * 128 * 72;
        __half* sV = sVb + st * 64 * 136;
        #pragma unroll
        for (int u = t; u < 1024; u += 128) {
            const int r = u >> 3, c8 = (u & 7) << 3;
            cp16(smem_u32(&sK[r * 72 + c8]),
                 k16 + (size_t)(b * Nn + j0 + r) * Dd + h * 64 + c8);
        }
        #pragma unroll
        for (int u = t; u < 1024; u += 128) {
            const int r = u >> 4, c8 = (u & 15) << 3;
            cp16(smem_u32(&sV[r * 136 + c8]),
                 vt16 + (size_t)(b * Dd + h * 64 + r) * Nn + j0 + c8);
        }
        cp_commit();
    };

    stage_tile(0, jbeg);

    for (int jt = 0; jt < njt; jt++) {
        const int j0 = jbeg + jt * TJA;
        cp_wait0();
        __syncthreads();
        if (jt + 1 < njt) stage_tile((jt + 1) & 1, j0 + TJA);

        const uint32_t* sK32 = (const uint32_t*)(sKb + (jt & 1) * 128 * 72);
        const uint32_t* sV32 = (const uint32_t*)(sVb + (jt & 1) * 64 * 136);

        // scores: fp16 1-term, 16 j-frags
        float s[16][4];
        #pragma unroll
        for (int jf = 0; jf < 16; jf++) {
            s[jf][0] = 0.f; s[jf][1] = 0.f; s[jf][2] = 0.f; s[jf][3] = 0.f;
            #pragma unroll
            for (int ks = 0; ks < 4; ks++) {
                const int o = (jf * 8 + gid) * 36 + ks * 8 + tig;
                uint32_t bh[2] = { sK32[o], sK32[o + 4] };
                mma16816h(s[jf], aq[ks], bh);
            }
        }
        // add rpe
        {
            const uint32_t* rp32 = (const uint32_t*)rpe;
            const size_t row0 = ((size_t)(b * Hh + h) * Nn + i0 + gid) * 512 + (j0 >> 1) + tig;
            const size_t row1 = row0 + 8 * 512;
            #pragma unroll
            for (int jf = 0; jf < 16; jf++) {
                uint32_t u0 = rp32[row0 + jf * 4];
                uint32_t u1 = rp32[row1 + jf * 4];
                float2 f0 = __half22float2(*(const __half2*)&u0);
                float2 f1 = __half22float2(*(const __half2*)&u1);
                s[jf][0] += f0.x; s[jf][1] += f0.y;
                s[jf][2] += f1.x; s[jf][3] += f1.y;
            }
        }

        // online softmax over 128 cols
        float mx0 = -1e30f, mx1 = -1e30f;
        #pragma unroll
        for (int jf = 0; jf < 16; jf++) {
            mx0 = fmaxf(mx0, fmaxf(s[jf][0], s[jf][1]));
            mx1 = fmaxf(mx1, fmaxf(s[jf][2], s[jf][3]));
        }
        mx0 = fmaxf(mx0, __shfl_xor_sync(0xffffffffu, mx0, 1));
        mx0 = fmaxf(mx0, __shfl_xor_sync(0xffffffffu, mx0, 2));
        mx1 = fmaxf(mx1, __shfl_xor_sync(0xffffffffu, mx1, 1));
        mx1 = fmaxf(mx1, __shfl_xor_sync(0xffffffffu, mx1, 2));
        const float M0 = fmaxf(m0, mx0), M1 = fmaxf(m1, mx1);
        const float sc0 = __expf(m0 - M0), sc1 = __expf(m1 - M1);
        float ls0 = 0.0f, ls1 = 0.0f;
        #pragma unroll
        for (int jf = 0; jf < 16; jf++) {
            s[jf][0] = __expf(s[jf][0] - M0); ls0 += s[jf][0];
            s[jf][1] = __expf(s[jf][1] - M0); ls0 += s[jf][1];
            s[jf][2] = __expf(s[jf][2] - M1); ls1 += s[jf][2];
            s[jf][3] = __expf(s[jf][3] - M1); ls1 += s[jf][3];
        }
        ls0 += __shfl_xor_sync(0xffffffffu, ls0, 1);
        ls0 += __shfl_xor_sync(0xffffffffu, ls0, 2);
        ls1 += __shfl_xor_sync(0xffffffffu, ls1, 1);
        ls1 += __shfl_xor_sync(0xffffffffu, ls1, 2);
        l0 = l0 * sc0 + ls0;
        l1 = l1 * sc1 + ls1;
        m0 = M0; m1 = M1;
        #pragma unroll
        for (int nf = 0; nf < 8; nf++) {
            acc[nf][0] *= sc0; acc[nf][1] *= sc0;
            acc[nf][2] *= sc1; acc[nf][3] *= sc1;
        }

        // P -> fp16 A-frags (8 k-frags of k16)
        uint32_t ph[8][4];
        #pragma unroll
        for (int kf = 0; kf < 8; kf++) {
            const int jE = 2 * kf, jO = 2 * kf + 1;
            ph[kf][0] = packh2(s[jE][0], s[jE][1]);
            ph[kf][1] = packh2(s[jE][2], s[jE][3]);
            ph[kf][2] = packh2(s[jO][0], s[jO][1]);
            ph[kf][3] = packh2(s[jO][2], s[jO][3]);
        }

        // AV fp16 1-term: k = 128 tok -> 8 k16 steps
        #pragma unroll
        for (int nf = 0; nf < 8; nf++) {
            #pragma unroll
            for (int kf = 0; kf < 8; kf++) {
                const int o = (nf * 8 + gid) * 68 + kf * 8 + tig;
                uint32_t bh[2] = { sV32[o], sV32[o + 4] };
                mma16816h(acc[nf], ph[kf], bh);
            }
        }
        __syncthreads();
    }

    float* pab = pacc + (size_t)sp * (Bb * Nn * Dd) + (size_t)b * (Nn * Dd);
    #pragma unroll
    for (int nf = 0; nf < 8; nf++) {
        const int ch = h * 64 + nf * 8 + 2 * tig;
        *(float2*)&pab[(size_t)(i0 + gid) * Dd + ch]     = make_float2(acc[nf][0], acc[nf][1]);
        *(float2*)&pab[(size_t)(i0 + gid + 8) * Dd + ch] = make_float2(acc[nf][2], acc[nf][3]);
    }
    if (tig == 0) {
        const size_t ix0 = (((size_t)sp * Bb + b) * Nn + i0 + gid) * Hh + h;
        const size_t ix1 = (((size_t)sp * Bb + b) * Nn + i0 + gid + 8) * Hh + h;
        pm[ix0] = m0; pl[ix0] = l0;
        pm[ix1] = m1; pl[ix1] = l1;
    }
}

// ---------------- combine partials -> ao fp16 ----------------
__global__ void attn_combine_kernel(const float* __restrict__ pacc,
                                    const float* __restrict__ pm,
                                    const float* __restrict__ pl,
                                    __half* __restrict__ ao16)
{
    const int i = blockIdx.x;
    const int b = blockIdx.y;
    const int t = threadIdx.x;
    __shared__ float sh_w[SPL][Hh];
    __shared__ float sh_invL[Hh];

    if (t < Hh) {
        float m[SPL], l[SPL];
        float M = -1e30f;
        #pragma unroll
        for (int s = 0; s < SPL; s++) {
            size_t idx = (((size_t)s * Bb + b) * Nn + i) * Hh + t;
            m[s] = pm[idx]; l[s] = pl[idx];
            M = fmaxf(M, m[s]);
        }
        float L = 0.0f;
        #pragma unroll
        for (int s = 0; s < SPL; s++) {
            float w = __expf(m[s] - M);
            sh_w[s][t] = w;
            L = fmaf(l[s], w, L);
        }
        sh_invL[t] = 1.0f / L;
    }
    __syncthreads();

    const int e0 = t, e1 = t + 256;
    const int he0 = t >> 6, he1 = he0 + 4;
    const size_t row = ((size_t)(b * Nn) + i) * Dd;
    float a0 = 0.0f, a1 = 0.0f;
    #pragma unroll
    for (int s = 0; s < SPL; s++) {
        const float* pab = pacc + (size_t)s * (Bb * Nn * Dd);
        a0 = fmaf(pab[row + e0], sh_w[s][he0], a0);
        a1 = fmaf(pab[row + e1], sh_w[s][he1], a1);
    }
    ao16[row + e0] = __float2half(a0 * sh_invL[he0]);
    ao16[row + e1] = __float2half(a1 * sh_invL[he1]);
}

// ---------------- residual + LayerNorm ----------------
template<int H16>
__global__ void ln_kernel(const float* __restrict__ x, const float* __restrict__ add,
                          const float* __restrict__ g, const float* __restrict__ bet,
                          float* __restrict__ out, __half* __restrict__ outH)
{
    const int row = blockIdx.x;
    const int t = threadIdx.x;
    const size_t base = (size_t)row * Dd;
    float v0 = x[base + t]       + add[base + t];
    float v1 = x[base + t + 256] + add[base + t + 256];
    float s  = v0 + v1;
    float s2 = v0 * v0 + v1 * v1;
    #pragma unroll
    for (int o = 16; o > 0; o >>= 1) {
        s  += __shfl_xor_sync(0xffffffffu, s,  o);
        s2 += __shfl_xor_sync(0xffffffffu, s2, o);
    }
    __shared__ float ws[8], ws2[8];
    __shared__ float mu_s, rs_s;
    if ((t & 31) == 0) { ws[t >> 5] = s; ws2[t >> 5] = s2; }
    __syncthreads();
    if (t == 0) {
        float S = 0.0f, S2 = 0.0f;
        #pragma unroll
        for (int w = 0; w < 8; w++) { S += ws[w]; S2 += ws2[w]; }
        float mu = S * (1.0f / 512.0f);
        float var = S2 * (1.0f / 512.0f) - mu * mu;
        mu_s = mu;
        rs_s = rsqrtf(var + 1e-5f);
    }
    __syncthreads();
    float o0 = (v0 - mu_s) * rs_s * g[t]       + bet[t];
    float o1 = (v1 - mu_s) * rs_s * g[t + 256] + bet[t + 256];
    out[base + t]       = o0;
    out[base + t + 256] = o1;
    if (H16) {
        outH[base + t]       = __float2half(o0);
        outH[base + t + 256] = __float2half(o1);
    }
}

// ---------------- launch ----------------
extern "C" void kernel_launch(void* const* d_in, const int* in_sizes, int n_in,
                              void* d_out, int out_size)
{
    (void)in_sizes; (void)n_in; (void)out_size;
    const float* x       = (const float*)d_in[0];
    const float* rel_pos = (const float*)d_in[1];
    const float* Wq = (const float*)d_in[2];  const float* bq = (const float*)d_in[3];
    const float* Wk = (const float*)d_in[4];  const float* bk = (const float*)d_in[5];
    const float* Wv = (const float*)d_in[6];  const float* bv = (const float*)d_in[7];
    const float* Wo = (const float*)d_in[8];  const float* bo = (const float*)d_in[9];
    const float* R1 = (const float*)d_in[10]; const float* rb1 = (const float*)d_in[11];
    const float* R2 = (const float*)d_in[12]; const float* rb2 = (const float*)d_in[13];
    const float* g1 = (const float*)d_in[14]; const float* b1 = (const float*)d_in[15];
    const float* g2 = (const float*)d_in[16]; const float* b2 = (const float*)d_in[17];
    const float* F1 = (const float*)d_in[18]; const float* fb1 = (const float*)d_in[19];
    const float* F2 = (const float*)d_in[20]; const float* fb2 = (const float*)d_in[21];
    float* outp = (float*)d_out;

    float *wo, *x1, *f2, *pacc, *pm, *pl, *bqkv;
    cudaGetSymbolAddress((void**)&wo,   g_wo);
    cudaGetSymbolAddress((void**)&x1,   g_x1);
    cudaGetSymbolAddress((void**)&f2,   g_f2);
    cudaGetSymbolAddress((void**)&pacc, g_pacc);
    cudaGetSymbolAddress((void**)&pm,   g_pm);
    cudaGetSymbolAddress((void**)&pl,   g_pl);
    cudaGetSymbolAddress((void**)&bqkv, g_bqkv);

    __half *x16, *q16, *k16, *v16, *vt16, *ao16, *x116, *h16;
    __half *wqkvt16, *woth16, *f1th16, *f2th16, *rpe;
    cudaGetSymbolAddress((void**)&x16,  g_x16);
    cudaGetSymbolAddress((void**)&q16,  g_q16);
    cudaGetSymbolAddress((void**)&k16,  g_k16);
    cudaGetSymbolAddress((void**)&v16,  g_v16);
    cudaGetSymbolAddress((void**)&vt16, g_vt16);
    cudaGetSymbolAddress((void**)&ao16, g_ao16);
    cudaGetSymbolAddress((void**)&x116, g_x116);
    cudaGetSymbolAddress((void**)&h16,  g_h16);
    cudaGetSymbolAddress((void**)&wqkvt16, g_wqkvt16);
    cudaGetSymbolAddress((void**)&woth16, g_woth16);
    cudaGetSymbolAddress((void**)&f1th16, g_f1th16);
    cudaGetSymbolAddress((void**)&f2th16, g_f2th16);
    cudaGetSymbolAddress((void**)&rpe,  g_rpe);

    const int M = Bb * Nn;
    dim3 tb(32, 8);

    constexpr int AS = 40;
    const int SMEM_F64  = (2 * 128 * AS + 2 * 64 * AS) * (int)sizeof(__half);
    const int SMEM_F128 = (2 * 128 * AS + 2 * 128 * AS) * (int)sizeof(__half);
    const int ATTN_SMEM = (2 * 128 * 72 + 2 * 64 * 136) * (int)sizeof(__half);  // 71680
    cudaFuncSetAttribute(gemm_f16_kernel<64,0>,  cudaFuncAttributeMaxDynamicSharedMemorySize, SMEM_F64);
    cudaFuncSetAttribute(gemm_f16_kernel<128,2>, cudaFuncAttributeMaxDynamicSharedMemorySize, SMEM_F128);
    cudaFuncSetAttribute(gemm_f16_kernel<128,3>, cudaFuncAttributeMaxDynamicSharedMemorySize, SMEM_F128);
    cudaFuncSetAttribute(attn_mma_kernel, cudaFuncAttributeMaxDynamicSharedMemorySize, ATTN_SMEM);

    // ---- fork: side stream runs rpe + Wo/FFN weight transposes ----
    cudaEventRecord(g_ss.fork, 0);
    cudaStreamWaitEvent(g_ss.s, g_ss.fork, 0);
    rpe_kernel<<<dim3(Nn / 128, Nn, Bb), 256, 0, g_ss.s>>>(rel_pos, R1, rb1, R2, rb2, rpe);
    transpose_f16_kernel<<<dim3(16, 16), tb, 0, g_ss.s>>>(Wo, woth16, Dd, Dd);
    transpose_f16_kernel<<<dim3(64, 16), tb, 0, g_ss.s>>>(F1, f1th16, Dd, FFN);
    transpose_f16_kernel<<<dim3(16, 64), tb, 0, g_ss.s>>>(F2, f2th16, FFN, Dd);
    cudaEventRecord(g_ss.join, g_ss.s);

    // ---- main stream: QKV path ----
    transpose_f16_qkv_kernel<<<dim3(16, 16, 3), tb>>>(Wq, Wk, Wv, bq, bk, bv, wqkvt16, bqkv);
    to_f16_kernel<<<(M * Dd / 4) / 256, 256>>>(x, x16);

    gemm_f16_kernel<128,3><<<dim3(3 * Dd / 128, M / 128), 256, SMEM_F128>>>(
        x16, wqkvt16, bqkv, nullptr, q16, k16, v16, M, Dd, 3 * Dd);
    vT16_kernel<<<dim3(Nn / 32, Dd / 32, Bb), tb>>>(v16, vt16);

    // ---- join ----
    cudaStreamWaitEvent(0, g_ss.join, 0);

    attn_mma_kernel<<<dim3(Nn / 64, Bb, Hh * SPL), 128, ATTN_SMEM>>>(
        q16, k16, vt16, rpe, pacc, pm, pl);
    attn_combine_kernel<<<dim3(Nn, Bb), 256>>>(pacc, pm, pl, ao16);

    gemm_f16_kernel<64,0><<<dim3(Dd / 64, M / 128), 256, SMEM_F64>>>(
        ao16, woth16, bo, wo, nullptr, nullptr, nullptr, M, Dd, Dd);
    ln_kernel<1><<<M, 256>>>(x, wo, g1, b1, x1, x116);

    gemm_f16_kernel<128,2><<<dim3(FFN / 128, M / 128), 256, SMEM_F128>>>(
        x116, f1th16, fb1, nullptr, h16, nullptr, nullptr, M, Dd, FFN);
    gemm_f16_kernel<64,0><<<dim3(Dd / 64, M / 128), 256, SMEM_F64>>>(
        h16, f2th16, fb2, f2, nullptr, nullptr, nullptr, M, FFN, Dd);
    ln_kernel<0><<<M, 256>>>(x1, f2, g2, b2, outp, nullptr);
}

// round 15
// speedup vs baseline: 1.0315x; 1.0315x over previous
#include <cuda_runtime.h>
#include <cuda_bf16.h>
#include <cuda_fp16.h>
#include <math.h>
#include <stdint.h>

#define Bb 2
#define Nn 1024
#define Dd 512
#define Hh 8
#define HD 64
#define FFN 2048
#define SPL 2
#define NSPLIT (Nn / SPL)

// ---------------- scratch ----------------
__device__ float g_wo [Bb*Nn*Dd];
__device__ float g_x1 [Bb*Nn*Dd];
__device__ float g_f2 [Bb*Nn*Dd];
__device__ float g_pacc[SPL*Bb*Nn*Dd];
__device__ float g_pm[SPL*Bb*Nn*Hh];
__device__ float g_pl[SPL*Bb*Nn*Hh];
__device__ float g_bqkv[3*Dd];

__device__ __half g_x16 [Bb*Nn*Dd];
__device__ __half g_q16 [Bb*Nn*Dd];          // scaled by 1/8
__device__ __half g_k16 [Bb*Nn*Dd];
__device__ __half g_v16 [Bb*Nn*Dd];          // row-major
__device__ __half g_vt16[Bb*Dd*Nn];          // transposed [b,ch,tok]
__device__ __half g_ao16[Bb*Nn*Dd];
__device__ __half g_x116[Bb*Nn*Dd];
__device__ __half g_h16 [Bb*Nn*FFN];
__device__ __half g_rpe[Bb*Hh*Nn*Nn];
__device__ __half g_wqkvt16[3*Dd*Dd];
__device__ __half g_woth16[Dd*Dd];
__device__ __half g_f1th16[Dd*FFN];
__device__ __half g_f2th16[FFN*Dd];

struct SideStream {
    cudaStream_t s = nullptr;
    cudaEvent_t fork = nullptr, join = nullptr;
    SideStream() {
        cudaStreamCreateWithFlags(&s, cudaStreamNonBlocking);
        cudaEventCreateWithFlags(&fork, cudaEventDisableTiming);
        cudaEventCreateWithFlags(&join, cudaEventDisableTiming);
    }
};
static SideStream g_ss;

__device__ __forceinline__ float gelu_exact(float x) {
    return 0.5f * x * (1.0f + erff(x * 0.70710678118654752f));
}
__device__ __forceinline__ uint32_t packh2(float a, float b) {
    __half2 h = __floats2half2_rn(a, b);
    return *(uint32_t*)&h;
}
__device__ __forceinline__ uint32_t f2tf(float f) {
    uint32_t r;
    asm("cvt.rna.tf32.f32 %0, %1;" : "=r"(r) : "f"(f));
    return r;
}
__device__ __forceinline__ uint32_t smem_u32(const void* p) {
    uint32_t a;
    asm("{ .reg .u64 t; cvta.to.shared.u64 t, %1; cvt.u32.u64 %0, t; }" : "=r"(a) : "l"(p));
    return a;
}
__device__ __forceinline__ void cp16(uint32_t saddr, const void* g) {
    asm volatile("cp.async.ca.shared.global [%0], [%1], 16;" :: "r"(saddr), "l"(g));
}
__device__ __forceinline__ void cp_commit() { asm volatile("cp.async.commit_group;" ::: "memory"); }
__device__ __forceinline__ void cp_wait0()  { asm volatile("cp.async.wait_group 0;" ::: "memory"); }

__device__ __forceinline__ void mma16816h(float* c, const uint32_t* a, const uint32_t* b) {
    asm volatile("mma.sync.aligned.m16n8k16.row.col.f32.f16.f16.f32 "
        "{%0,%1,%2,%3}, {%4,%5,%6,%7}, {%8,%9}, {%0,%1,%2,%3};"
        : "+f"(c[0]), "+f"(c[1]), "+f"(c[2]), "+f"(c[3])
        : "r"(a[0]), "r"(a[1]), "r"(a[2]), "r"(a[3]), "r"(b[0]), "r"(b[1]));
}
__device__ __forceinline__ void mma1688tf(float* c, const uint32_t* a, const uint32_t* b) {
    asm volatile("mma.sync.aligned.m16n8k8.row.col.f32.tf32.tf32.f32 "
        "{%0,%1,%2,%3}, {%4,%5,%6,%7}, {%8,%9}, {%0,%1,%2,%3};"
        : "+f"(c[0]), "+f"(c[1]), "+f"(c[2]), "+f"(c[3])
        : "r"(a[0]), "r"(a[1]), "r"(a[2]), "r"(a[3]), "r"(b[0]), "r"(b[1]));
}

// ============ fp16 1-term GEMM ============
// EPI: 0 = fp32 row-major; 2 = GELU -> fp16; 3 = QKV routing (q scaled 1/8, k, v fp16).
template<int BN, int EPI>
__global__ __launch_bounds__(256)
void gemm_f16_kernel(const __half* __restrict__ Af,
                     const __half* __restrict__ Bf,
                     const float* __restrict__ bias,
                     float* __restrict__ outF, __half* __restrict__ outH,
                     __half* __restrict__ outK, __half* __restrict__ outV,
                     int M, int K, int Nc)
{
    constexpr int BM = 128;
    constexpr int WM = (BN == 128) ? 2 : 4;
    constexpr int WN = 8 / WM;
    constexpr int WTM = BM / WM;
    constexpr int WTN = BN / WN;
    constexpr int MT = WTM / 16;
    constexpr int NT = WTN / 8;
    constexpr int AS = 40;

    extern __shared__ __half smh[];
    __half* sAbase = smh;
    __half* sBbase = smh + 2 * BM * AS;

    const int t = threadIdx.x;
    const int wid = t >> 5, lane = t & 31;
    const int gid = lane >> 2, tig = lane & 3;
    const int wm = wid % WM, wn = wid / WM;
    const int mtile = blockIdx.y * BM, ntile = blockIdx.x * BN;

    float acc[MT][NT][4];
    #pragma unroll
    for (int i = 0; i < MT; i++)
        #pragma unroll
        for (int j = 0; j < NT; j++)
            #pragma unroll
            for (int r = 0; r < 4; r++) acc[i][j][r] = 0.0f;

    const int lr = t >> 2;
    const int lc = (t & 3) << 3;
    const int nch = K >> 5;

    auto load_stage = [&](int st, int k0) {
        __half* sA = sAbase + st * BM * AS;
        __half* sB = sBbase + st * BN * AS;
        #pragma unroll
        for (int rep = 0; rep < BM / 64; rep++) {
            const int rr = lr + rep * 64;
            cp16(smem_u32(sA + rr * AS + lc), Af + (size_t)(mtile + rr) * K + k0 + lc);
        }
        #pragma unroll
        for (int rep = 0; rep < BN / 64; rep++) {
            const int rr = lr + rep * 64;
            cp16(smem_u32(sB + rr * AS + lc), Bf + (size_t)(ntile + rr) * K + k0 + lc);
        }
        cp_commit();
    };

    load_stage(0, 0);

    for (int c = 0; c < nch; c++) {
        cp_wait0();
        __syncthreads();
        if (c + 1 < nch) load_stage((c + 1) & 1, (c + 1) << 5);

        const int st = c & 1;
        const __half* sA = sAbase + st * BM * AS;
        const __half* sB = sBbase + st * BN * AS;

        #pragma unroll
        for (int kk = 0; kk < 2; kk++) {
            const int kb = kk * 16 + 2 * tig;
            uint32_t af[MT][4], bf[NT][2];
            #pragma unroll
            for (int i = 0; i < MT; i++) {
                const int row = wm * WTM + i * 16 + gid;
                const __half* p = sA + row * AS + kb;
                af[i][0] = *(const uint32_t*)p;
                af[i][1] = *(const uint32_t*)(p + 8 * AS);
                af[i][2] = *(const uint32_t*)(p + 8);
                af[i][3] = *(const uint32_t*)(p + 8 * AS + 8);
            }
            #pragma unroll
            for (int j = 0; j < NT; j++) {
                const int nrow = wn * WTN + j * 8 + gid;
                const __half* p = sB + nrow * AS + kb;
                bf[j][0] = *(const uint32_t*)p;
                bf[j][1] = *(const uint32_t*)(p + 8);
            }
            #pragma unroll
            for (int i = 0; i < MT; i++)
                #pragma unroll
                for (int j = 0; j < NT; j++)
                    mma16816h(acc[i][j], af[i], bf[j]);
        }
        __syncthreads();
    }

    #pragma unroll
    for (int i = 0; i < MT; i++) {
        const int r0 = mtile + wm * WTM + i * 16 + gid;
        const int r1 = r0 + 8;
        #pragma unroll
        for (int j = 0; j < NT; j++) {
            const int n = ntile + wn * WTN + j * 8 + 2 * tig;
            const float b0 = bias[n], b1 = bias[n + 1];
            float v00 = acc[i][j][0] + b0, v01 = acc[i][j][1] + b1;
            float v10 = acc[i][j][2] + b0, v11 = acc[i][j][3] + b1;
            if (EPI == 0) {
                *(float2*)&outF[(size_t)r0 * Nc + n] = make_float2(v00, v01);
                *(float2*)&outF[(size_t)r1 * Nc + n] = make_float2(v10, v11);
            } else if (EPI == 2) {
                __half2 o0 = __floats2half2_rn(gelu_exact(v00), gelu_exact(v01));
                __half2 o1 = __floats2half2_rn(gelu_exact(v10), gelu_exact(v11));
                *(__half2*)&outH[(size_t)r0 * Nc + n] = o0;
                *(__half2*)&outH[(size_t)r1 * Nc + n] = o1;
            } else { // EPI 3: QKV routing
                if (n < Dd) {
                    *(uint32_t*)&outH[(size_t)r0 * Dd + n] = packh2(v00 * 0.125f, v01 * 0.125f);
                    *(uint32_t*)&outH[(size_t)r1 * Dd + n] = packh2(v10 * 0.125f, v11 * 0.125f);
                } else if (n < 2 * Dd) {
                    const int ch = n - Dd;
                    *(uint32_t*)&outK[(size_t)r0 * Dd + ch] = packh2(v00, v01);
                    *(uint32_t*)&outK[(size_t)r1 * Dd + ch] = packh2(v10, v11);
                } else {
                    const int ch = n - 2 * Dd;
                    *(uint32_t*)&outV[(size_t)r0 * Dd + ch] = packh2(v00, v01);
                    *(uint32_t*)&outV[(size_t)r1 * Dd + ch] = packh2(v10, v11);
                }
            }
        }
    }
}

// ============ weight prep: fp32 [K,Nc] -> fp16 [Nc,K] ============
__global__ void transpose_f16_kernel(const float* __restrict__ W,
                                     __half* __restrict__ T,
                                     int K, int Nc)
{
    __shared__ float tile[32][33];
    const int n0 = blockIdx.x * 32, k0 = blockIdx.y * 32;
    const int tx = threadIdx.x, ty = threadIdx.y;
    #pragma unroll
    for (int dy = 0; dy < 32; dy += 8)
        tile[ty + dy][tx] = W[(size_t)(k0 + ty + dy) * Nc + n0 + tx];
    __syncthreads();
    #pragma unroll
    for (int dy = 0; dy < 32; dy += 8) {
        const size_t o = (size_t)(n0 + ty + dy) * K + k0 + tx;
        T[o] = __float2half_rn(tile[tx][ty + dy]);
    }
}

// QKV weight transpose + bias concat
__global__ void transpose_f16_qkv_kernel(const float* __restrict__ Wq,
                                         const float* __restrict__ Wk,
                                         const float* __restrict__ Wv,
                                         const float* __restrict__ bq,
                                         const float* __restrict__ bk,
                                         const float* __restrict__ bv,
                                         __half* __restrict__ T,
                                         float* __restrict__ bqkv)
{
    __shared__ float tile[32][33];
    const int z = blockIdx.z;
    const float* W = (z == 0) ? Wq : (z == 1) ? Wk : Wv;
    const size_t woff = (size_t)z * Dd * Dd;
    const int n0 = blockIdx.x * 32, k0 = blockIdx.y * 32;
    const int tx = threadIdx.x, ty = threadIdx.y;
    if (blockIdx.y == 0 && ty == 0) {
        const float* bsrc = (z == 0) ? bq : (z == 1) ? bk : bv;
        bqkv[z * Dd + n0 + tx] = bsrc[n0 + tx];
    }
    #pragma unroll
    for (int dy = 0; dy < 32; dy += 8)
        tile[ty + dy][tx] = W[(size_t)(k0 + ty + dy) * Dd + n0 + tx];
    __syncthreads();
    #pragma unroll
    for (int dy = 0; dy < 32; dy += 8) {
        const size_t o = woff + (size_t)(n0 + ty + dy) * Dd + k0 + tx;
        T[o] = __float2half_rn(tile[tx][ty + dy]);
    }
}

// ============ fp32 -> fp16 elementwise ============
__global__ void to_f16_kernel(const float* __restrict__ in, __half* __restrict__ out)
{
    const int i = blockIdx.x * 256 + threadIdx.x;
    float4 v = ((const float4*)in)[i];
    ((uint32_t*)out)[i * 2 + 0] = packh2(v.x, v.y);
    ((uint32_t*)out)[i * 2 + 1] = packh2(v.z, v.w);
}

// ============ V fp16 row-major -> V^T fp16 [b,ch,tok] ============
__global__ void vT16_kernel(const __half* __restrict__ v16,
                            __half* __restrict__ vt16)
{
    __shared__ __half tile[32][40];
    const int tok0 = blockIdx.x * 32, ch0 = blockIdx.y * 32, b = blockIdx.z;
    const int tx = threadIdx.x, ty = threadIdx.y;
    #pragma unroll
    for (int dy = 0; dy < 32; dy += 8)
        tile[ty + dy][tx] = v16[((size_t)(b * Nn + tok0 + ty + dy)) * Dd + ch0 + tx];
    __syncthreads();
    #pragma unroll
    for (int dy = 0; dy < 32; dy += 8) {
        const size_t o = ((size_t)(b * Dd + ch0 + ty + dy)) * Nn + tok0 + tx;
        vt16[o] = tile[tx][ty + dy];
    }
}

// ============ RPE: tf32 layer1 -> relu -> fp16 layer2 (tensor) ============
__global__ __launch_bounds__(256)
void rpe_kernel(const float* __restrict__ rel_pos,
                const float* __restrict__ R1, const float* __restrict__ rb1,
                const float* __restrict__ R2, const float* __restrict__ rb2,
                __half* __restrict__ rpe)
{
    __shared__ __half sh_out[8][128];

    const int j0 = blockIdx.x * 128;
    const int i  = blockIdx.y;
    const int b  = blockIdx.z;
    const int t  = threadIdx.x;
    const int w = t >> 5, lane = t & 31;
    const int gid = lane >> 2, tig = lane & 3;
    const int jw = w * 16;

    uint32_t b1f[8];
    #pragma unroll
    for (int ut = 0; ut < 8; ut++) b1f[ut] = f2tf(R1[tig * 64 + ut * 8 + gid]);

    const float* rp = rel_pos + ((size_t)(b * Nn + i) * Nn + j0 + jw) * 4;
    uint32_t a1f[4];
    a1f[0] = f2tf(rp[gid * 4 + tig]);
    a1f[1] = f2tf(rp[(gid + 8) * 4 + tig]);
    a1f[2] = 0u;
    a1f[3] = 0u;

    float c1[8][4];
    #pragma unroll
    for (int ut = 0; ut < 8; ut++) {
        c1[ut][0] = 0.f; c1[ut][1] = 0.f; c1[ut][2] = 0.f; c1[ut][3] = 0.f;
        uint32_t bb[2] = { b1f[ut], 0u };
        mma1688tf(c1[ut], a1f, bb);
        const float r0 = rb1[ut * 8 + 2 * tig], r1 = rb1[ut * 8 + 2 * tig + 1];
        c1[ut][0] = fmaxf(c1[ut][0] + r0, 0.f);
        c1[ut][1] = fmaxf(c1[ut][1] + r1, 0.f);
        c1[ut][2] = fmaxf(c1[ut][2] + r0, 0.f);
        c1[ut][3] = fmaxf(c1[ut][3] + r1, 0.f);
    }

    float c2[4] = {0.f, 0.f, 0.f, 0.f};
    #pragma unroll
    for (int ks = 0; ks < 4; ks++) {
        uint32_t a2[4];
        a2[0] = packh2(c1[2 * ks][0],     c1[2 * ks][1]);
        a2[1] = packh2(c1[2 * ks][2],     c1[2 * ks][3]);
        a2[2] = packh2(c1[2 * ks + 1][0], c1[2 * ks + 1][1]);
        a2[3] = packh2(c1[2 * ks + 1][2], c1[2 * ks + 1][3]);
        uint32_t b2[2];
        b2[0] = packh2(R2[(16 * ks + 2 * tig) * 8 + gid],     R2[(16 * ks + 2 * tig + 1) * 8 + gid]);
        b2[1] = packh2(R2[(16 * ks + 8 + 2 * tig) * 8 + gid], R2[(16 * ks + 9 + 2 * tig) * 8 + gid]);
        mma16816h(c2, a2, b2);
    }
    const float rbA = rb2[2 * tig], rbB = rb2[2 * tig + 1];
    sh_out[2 * tig    ][jw + gid]     = __float2half(c2[0] + rbA);
    sh_out[2 * tig + 1][jw + gid]     = __float2half(c2[1] + rbB);
    sh_out[2 * tig    ][jw + gid + 8] = __float2half(c2[2] + rbA);
    sh_out[2 * tig + 1][jw + gid + 8] = __float2half(c2[3] + rbB);
    __syncthreads();

    const uint32_t* src = (const uint32_t*)sh_out;
    #pragma unroll
    for (int u = t; u < 512; u += 256) {
        const int hh = u >> 6, col = u & 63;
        ((uint32_t*)(rpe + (((size_t)(b * Hh + hh) * Nn + i) * Nn + j0)))[col] = src[hh * 64 + col];
    }
}

// ============ attention: TJ=64, 8 warps/CTA (128 i-rows), cp.async double-buffered ============
__global__ __launch_bounds__(256)
void attn_mma_kernel(const __half* __restrict__ q16,
                     const __half* __restrict__ k16,
                     const __half* __restrict__ vt16,
                     const __half* __restrict__ rpe,
                     float* __restrict__ pacc, float* __restrict__ pm, float* __restrict__ pl)
{
    __shared__ __half sK[2][64 * 72];
    __shared__ __half sV[2][64 * 72];

    const int it = blockIdx.x;           // 128-row i-tile
    const int b  = blockIdx.y;
    const int h  = blockIdx.z >> 1;
    const int sp = blockIdx.z & 1;
    const int t = threadIdx.x;
    const int w = t >> 5, lane = t & 31;
    const int gid = lane >> 2, tig = lane & 3;
    const int i0 = it * 128 + w * 16;     // warp's first query row (8 warps x 16 rows)
    const int jbeg = sp * NSPLIT;
    const int njt = NSPLIT / 64;

    // preload q A-frags (fp16) for this warp's 16 rows
    uint32_t aq[4][4];
    {
        const __half* qb = q16 + (size_t)(b * Nn) * Dd + h * 64;
        #pragma unroll
        for (int ks = 0; ks < 4; ks++) {
            const int kb = ks * 16 + 2 * tig;
            const __half* p0 = qb + (size_t)(i0 + gid) * Dd + kb;
            const __half* p1 = qb + (size_t)(i0 + gid + 8) * Dd + kb;
            aq[ks][0] = *(const uint32_t*)p0;
            aq[ks][1] = *(const uint32_t*)p1;
            aq[ks][2] = *(const uint32_t*)(p0 + 8);
            aq[ks][3] = *(const uint32_t*)(p1 + 8);
        }
    }

    float acc[8][4];
    #pragma unroll
    for (int nf = 0; nf < 8; nf++)
        #pragma unroll
        for (int r = 0; r < 4; r++) acc[nf][r] = 0.0f;
    float m0 = -1e30f, m1 = -1e30f, l0 = 0.0f, l1 = 0.0f;

    // stage K [64j x 64ch], V^T [64ch x 64tok] with 256 threads
    auto stage_tile = [&](int st, int j0) {
        #pragma unroll
        for (int u = t; u < 512; u += 256) {
            const int r = u >> 3, c8 = (u & 7) << 3;
            cp16(smem_u32(&sK[st][r * 72 + c8]),
                 k16 + (size_t)(b * Nn + j0 + r) * Dd + h * 64 + c8);
        }
        #pragma unroll
        for (int u = t; u < 512; u += 256) {
            const int r = u >> 3, c8 = (u & 7) << 3;
            cp16(smem_u32(&sV[st][r * 72 + c8]),
                 vt16 + (size_t)(b * Dd + h * 64 + r) * Nn + j0 + c8);
        }
        cp_commit();
    };

    stage_tile(0, jbeg);

    for (int jt = 0; jt < njt; jt++) {
        const int j0 = jbeg + jt * 64;
        cp_wait0();
        __syncthreads();
        if (jt + 1 < njt) stage_tile((jt + 1) & 1, j0 + 64);

        const uint32_t* sK32 = (const uint32_t*)sK[jt & 1];
        const uint32_t* sV32 = (const uint32_t*)sV[jt & 1];

        // scores: fp16 1-term
        float s[8][4];
        #pragma unroll
        for (int jf = 0; jf < 8; jf++) {
            s[jf][0] = 0.f; s[jf][1] = 0.f; s[jf][2] = 0.f; s[jf][3] = 0.f;
            #pragma unroll
            for (int ks = 0; ks < 4; ks++) {
                const int o = (jf * 8 + gid) * 36 + ks * 8 + tig;
                uint32_t bh[2] = { sK32[o], sK32[o + 4] };
                mma16816h(s[jf], aq[ks], bh);
            }
        }
        // add rpe
        {
            const uint32_t* rp32 = (const uint32_t*)rpe;
            const size_t row0 = ((size_t)(b * Hh + h) * Nn + i0 + gid) * 512 + (j0 >> 1) + tig;
            const size_t row1 = row0 + 8 * 512;
            #pragma unroll
            for (int jf = 0; jf < 8; jf++) {
                uint32_t u0 = rp32[row0 + jf * 4];
                uint32_t u1 = rp32[row1 + jf * 4];
                float2 f0 = __half22float2(*(const __half2*)&u0);
                float2 f1 = __half22float2(*(const __half2*)&u1);
                s[jf][0] += f0.x; s[jf][1] += f0.y;
                s[jf][2] += f1.x; s[jf][3] += f1.y;
            }
        }

        // online softmax
        float mx0 = -1e30f, mx1 = -1e30f;
        #pragma unroll
        for (int jf = 0; jf < 8; jf++) {
            mx0 = fmaxf(mx0, fmaxf(s[jf][0], s[jf][1]));
            mx1 = fmaxf(mx1, fmaxf(s[jf][2], s[jf][3]));
        }
        mx0 = fmaxf(mx0, __shfl_xor_sync(0xffffffffu, mx0, 1));
        mx0 = fmaxf(mx0, __shfl_xor_sync(0xffffffffu, mx0, 2));
        mx1 = fmaxf(mx1, __shfl_xor_sync(0xffffffffu, mx1, 1));
        mx1 = fmaxf(mx1, __shfl_xor_sync(0xffffffffu, mx1, 2));
        const float M0 = fmaxf(m0, mx0), M1 = fmaxf(m1, mx1);
        const float sc0 = __expf(m0 - M0), sc1 = __expf(m1 - M1);
        float ls0 = 0.0f, ls1 = 0.0f;
        #pragma unroll
        for (int jf = 0; jf < 8; jf++) {
            s[jf][0] = __expf(s[jf][0] - M0); ls0 += s[jf][0];
            s[jf][1] = __expf(s[jf][1] - M0); ls0 += s[jf][1];
            s[jf][2] = __expf(s[jf][2] - M1); ls1 += s[jf][2];
            s[jf][3] = __expf(s[jf][3] - M1); ls1 += s[jf][3];
        }
        ls0 += __shfl_xor_sync(0xffffffffu, ls0, 1);
        ls0 += __shfl_xor_sync(0xffffffffu, ls0, 2);
        ls1 += __shfl_xor_sync(0xffffffffu, ls1, 1);
        ls1 += __shfl_xor_sync(0xffffffffu, ls1, 2);
        l0 = l0 * sc0 + ls0;
        l1 = l1 * sc1 + ls1;
        m0 = M0; m1 = M1;
        #pragma unroll
        for (int nf = 0; nf < 8; nf++) {
            acc[nf][0] *= sc0; acc[nf][1] *= sc0;
            acc[nf][2] *= sc1; acc[nf][3] *= sc1;
        }

        // P -> fp16 A-frags
        uint32_t ph[4][4];
        #pragma unroll
        for (int kf = 0; kf < 4; kf++) {
            const int jE = 2 * kf, jO = 2 * kf + 1;
            ph[kf][0] = packh2(s[jE][0], s[jE][1]);
            ph[kf][1] = packh2(s[jE][2], s[jE][3]);
            ph[kf][2] = packh2(s[jO][0], s[jO][1]);
            ph[kf][3] = packh2(s[jO][2], s[jO][3]);
        }

        // AV fp16 1-term
        #pragma unroll
        for (int nf = 0; nf < 8; nf++) {
            #pragma unroll
            for (int kf = 0; kf < 4; kf++) {
                const int o = (nf * 8 + gid) * 36 + kf * 8 + tig;
                uint32_t bh[2] = { sV32[o], sV32[o + 4] };
                mma16816h(acc[nf], ph[kf], bh);
            }
        }
        __syncthreads();
    }

    float* pab = pacc + (size_t)sp * (Bb * Nn * Dd) + (size_t)b * (Nn * Dd);
    #pragma unroll
    for (int nf = 0; nf < 8; nf++) {
        const int ch = h * 64 + nf * 8 + 2 * tig;
        *(float2*)&pab[(size_t)(i0 + gid) * Dd + ch]     = make_float2(acc[nf][0], acc[nf][1]);
        *(float2*)&pab[(size_t)(i0 + gid + 8) * Dd + ch] = make_float2(acc[nf][2], acc[nf][3]);
    }
    if (tig == 0) {
        const size_t ix0 = (((size_t)sp * Bb + b) * Nn + i0 + gid) * Hh + h;
        const size_t ix1 = (((size_t)sp * Bb + b) * Nn + i0 + gid + 8) * Hh + h;
        pm[ix0] = m0; pl[ix0] = l0;
        pm[ix1] = m1; pl[ix1] = l1;
    }
}

// ---------------- combine partials -> ao fp16 ----------------
__global__ void attn_combine_kernel(const float* __restrict__ pacc,
                                    const float* __restrict__ pm,
                                    const float* __restrict__ pl,
                                    __half* __restrict__ ao16)
{
    const int i = blockIdx.x;
    const int b = blockIdx.y;
    const int t = threadIdx.x;
    __shared__ float sh_w[SPL][Hh];
    __shared__ float sh_invL[Hh];

    if (t < Hh) {
        float m[SPL], l[SPL];
        float M = -1e30f;
        #pragma unroll
        for (int s = 0; s < SPL; s++) {
            size_t idx = (((size_t)s * Bb + b) * Nn + i) * Hh + t;
            m[s] = pm[idx]; l[s] = pl[idx];
            M = fmaxf(M, m[s]);
        }
        float L = 0.0f;
        #pragma unroll
        for (int s = 0; s < SPL; s++) {
            float w = __expf(m[s] - M);
            sh_w[s][t] = w;
            L = fmaf(l[s], w, L);
        }
        sh_invL[t] = 1.0f / L;
    }
    __syncthreads();

    const int e0 = t, e1 = t + 256;
    const int he0 = t >> 6, he1 = he0 + 4;
    const size_t row = ((size_t)(b * Nn) + i) * Dd;
    float a0 = 0.0f, a1 = 0.0f;
    #pragma unroll
    for (int s = 0; s < SPL; s++) {
        const float* pab = pacc + (size_t)s * (Bb * Nn * Dd);
        a0 = fmaf(pab[row + e0], sh_w[s][he0], a0);
        a1 = fmaf(pab[row + e1], sh_w[s][he1], a1);
    }
    ao16[row + e0] = __float2half(a0 * sh_invL[he0]);
    ao16[row + e1] = __float2half(a1 * sh_invL[he1]);
}

// ---------------- residual + LayerNorm ----------------
template<int H16>
__global__ void ln_kernel(const float* __restrict__ x, const float* __restrict__ add,
                          const float* __restrict__ g, const float* __restrict__ bet,
                          float* __restrict__ out, __half* __restrict__ outH)
{
    const int row = blockIdx.x;
    const int t = threadIdx.x;
    const size_t base = (size_t)row * Dd;
    float v0 = x[base + t]       + add[base + t];
    float v1 = x[base + t + 256] + add[base + t + 256];
    float s  = v0 + v1;
    float s2 = v0 * v0 + v1 * v1;
    #pragma unroll
    for (int o = 16; o > 0; o >>= 1) {
        s  += __shfl_xor_sync(0xffffffffu, s,  o);
        s2 += __shfl_xor_sync(0xffffffffu, s2, o);
    }
    __shared__ float ws[8], ws2[8];
    __shared__ float mu_s, rs_s;
    if ((t & 31) == 0) { ws[t >> 5] = s; ws2[t >> 5] = s2; }
    __syncthreads();
    if (t == 0) {
        float S = 0.0f, S2 = 0.0f;
        #pragma unroll
        for (int w = 0; w < 8; w++) { S += ws[w]; S2 += ws2[w]; }
        float mu = S * (1.0f / 512.0f);
        float var = S2 * (1.0f / 512.0f) - mu * mu;
        mu_s = mu;
        rs_s = rsqrtf(var + 1e-5f);
    }
    __syncthreads();
    float o0 = (v0 - mu_s) * rs_s * g[t]       + bet[t];
    float o1 = (v1 - mu_s) * rs_s * g[t + 256] + bet[t + 256];
    out[base + t]       = o0;
    out[base + t + 256] = o1;
    if (H16) {
        outH[base + t]       = __float2half(o0);
        outH[base + t + 256] = __float2half(o1);
    }
}

// ---------------- launch ----------------
extern "C" void kernel_launch(void* const* d_in, const int* in_sizes, int n_in,
                              void* d_out, int out_size)
{
    (void)in_sizes; (void)n_in; (void)out_size;
    const float* x       = (const float*)d_in[0];
    const float* rel_pos = (const float*)d_in[1];
    const float* Wq = (const float*)d_in[2];  const float* bq = (const float*)d_in[3];
    const float* Wk = (const float*)d_in[4];  const float* bk = (const float*)d_in[5];
    const float* Wv = (const float*)d_in[6];  const float* bv = (const float*)d_in[7];
    const float* Wo = (const float*)d_in[8];  const float* bo = (const float*)d_in[9];
    const float* R1 = (const float*)d_in[10]; const float* rb1 = (const float*)d_in[11];
    const float* R2 = (const float*)d_in[12]; const float* rb2 = (const float*)d_in[13];
    const float* g1 = (const float*)d_in[14]; const float* b1 = (const float*)d_in[15];
    const float* g2 = (const float*)d_in[16]; const float* b2 = (const float*)d_in[17];
    const float* F1 = (const float*)d_in[18]; const float* fb1 = (const float*)d_in[19];
    const float* F2 = (const float*)d_in[20]; const float* fb2 = (const float*)d_in[21];
    float* outp = (float*)d_out;

    float *wo, *x1, *f2, *pacc, *pm, *pl, *bqkv;
    cudaGetSymbolAddress((void**)&wo,   g_wo);
    cudaGetSymbolAddress((void**)&x1,   g_x1);
    cudaGetSymbolAddress((void**)&f2,   g_f2);
    cudaGetSymbolAddress((void**)&pacc, g_pacc);
    cudaGetSymbolAddress((void**)&pm,   g_pm);
    cudaGetSymbolAddress((void**)&pl,   g_pl);
    cudaGetSymbolAddress((void**)&bqkv, g_bqkv);

    __half *x16, *q16, *k16, *v16, *vt16, *ao16, *x116, *h16;
    __half *wqkvt16, *woth16, *f1th16, *f2th16, *rpe;
    cudaGetSymbolAddress((void**)&x16,  g_x16);
    cudaGetSymbolAddress((void**)&q16,  g_q16);
    cudaGetSymbolAddress((void**)&k16,  g_k16);
    cudaGetSymbolAddress((void**)&v16,  g_v16);
    cudaGetSymbolAddress((void**)&vt16, g_vt16);
    cudaGetSymbolAddress((void**)&ao16, g_ao16);
    cudaGetSymbolAddress((void**)&x116, g_x116);
    cudaGetSymbolAddress((void**)&h16,  g_h16);
    cudaGetSymbolAddress((void**)&wqkvt16, g_wqkvt16);
    cudaGetSymbolAddress((void**)&woth16, g_woth16);
    cudaGetSymbolAddress((void**)&f1th16, g_f1th16);
    cudaGetSymbolAddress((void**)&f2th16, g_f2th16);
    cudaGetSymbolAddress((void**)&rpe,  g_rpe);

    const int M = Bb * Nn;
    dim3 tb(32, 8);

    constexpr int AS = 40;
    const int SMEM_F64  = (2 * 128 * AS + 2 * 64 * AS) * (int)sizeof(__half);
    const int SMEM_F128 = (2 * 128 * AS + 2 * 128 * AS) * (int)sizeof(__half);
    cudaFuncSetAttribute(gemm_f16_kernel<64,0>,  cudaFuncAttributeMaxDynamicSharedMemorySize, SMEM_F64);
    cudaFuncSetAttribute(gemm_f16_kernel<128,2>, cudaFuncAttributeMaxDynamicSharedMemorySize, SMEM_F128);
    cudaFuncSetAttribute(gemm_f16_kernel<128,3>, cudaFuncAttributeMaxDynamicSharedMemorySize, SMEM_F128);

    // ---- fork: side stream runs rpe + Wo/FFN weight transposes ----
    cudaEventRecord(g_ss.fork, 0);
    cudaStreamWaitEvent(g_ss.s, g_ss.fork, 0);
    rpe_kernel<<<dim3(Nn / 128, Nn, Bb), 256, 0, g_ss.s>>>(rel_pos, R1, rb1, R2, rb2, rpe);
    transpose_f16_kernel<<<dim3(16, 16), tb, 0, g_ss.s>>>(Wo, woth16, Dd, Dd);
    transpose_f16_kernel<<<dim3(64, 16), tb, 0, g_ss.s>>>(F1, f1th16, Dd, FFN);
    transpose_f16_kernel<<<dim3(16, 64), tb, 0, g_ss.s>>>(F2, f2th16, FFN, Dd);
    cudaEventRecord(g_ss.join, g_ss.s);

    // ---- main stream: QKV path ----
    transpose_f16_qkv_kernel<<<dim3(16, 16, 3), tb>>>(Wq, Wk, Wv, bq, bk, bv, wqkvt16, bqkv);
    to_f16_kernel<<<(M * Dd / 4) / 256, 256>>>(x, x16);

    gemm_f16_kernel<128,3><<<dim3(3 * Dd / 128, M / 128), 256, SMEM_F128>>>(
        x16, wqkvt16, bqkv, nullptr, q16, k16, v16, M, Dd, 3 * Dd);
    vT16_kernel<<<dim3(Nn / 32, Dd / 32, Bb), tb>>>(v16, vt16);

    // ---- join ----
    cudaStreamWaitEvent(0, g_ss.join, 0);

    attn_mma_kernel<<<dim3(Nn / 128, Bb, Hh * SPL), 256>>>(q16, k16, vt16, rpe, pacc, pm, pl);
    attn_combine_kernel<<<dim3(Nn, Bb), 256>>>(pacc, pm, pl, ao16);

    gemm_f16_kernel<64,0><<<dim3(Dd / 64, M / 128), 256, SMEM_F64>>>(
        ao16, woth16, bo, wo, nullptr, nullptr, nullptr, M, Dd, Dd);
    ln_kernel<1><<<M, 256>>>(x, wo, g1, b1, x1, x116);

    gemm_f16_kernel<128,2><<<dim3(FFN / 128, M / 128), 256, SMEM_F128>>>(
        x116, f1th16, fb1, nullptr, h16, nullptr, nullptr, M, Dd, FFN);
    gemm_f16_kernel<64,0><<<dim3(Dd / 64, M / 128), 256, SMEM_F64>>>(
        h16, f2th16, fb2, f2, nullptr, nullptr, nullptr, M, FFN, Dd);
    ln_kernel<0><<<M, 256>>>(x1, f2, g2, b2, outp, nullptr);
}

// round 16
// speedup vs baseline: 1.1133x; 1.0793x over previous
#include <cuda_runtime.h>
#include <cuda_bf16.h>
#include <cuda_fp16.h>
#include <math.h>
#include <stdint.h>

#define Bb 2
#define Nn 1024
#define Dd 512
#define Hh 8
#define HD 64
#define FFN 2048
#define SPL 2
#define NSPLIT (Nn / SPL)

// ---------------- scratch ----------------
__device__ float g_wo [Bb*Nn*Dd];
__device__ float g_x1 [Bb*Nn*Dd];
__device__ float g_f2 [Bb*Nn*Dd];
__device__ float g_pacc[SPL*Bb*Nn*Dd];
__device__ float g_pm[SPL*Bb*Nn*Hh];
__device__ float g_pl[SPL*Bb*Nn*Hh];
__device__ float g_bqkv[3*Dd];

__device__ __half g_x16 [Bb*Nn*Dd];
__device__ __half g_q16 [Bb*Nn*Dd];          // scaled by 1/8
__device__ __half g_k16 [Bb*Nn*Dd];
__device__ __half g_v16 [Bb*Nn*Dd];          // row-major
__device__ __half g_vt16[Bb*Dd*Nn];          // transposed [b,ch,tok]
__device__ __half g_ao16[Bb*Nn*Dd];
__device__ __half g_x116[Bb*Nn*Dd];
__device__ __half g_h16 [Bb*Nn*FFN];
__device__ __half g_rpe[Bb*Hh*Nn*Nn];
__device__ __half g_wqkvt16[3*Dd*Dd];
__device__ __half g_woth16[Dd*Dd];
__device__ __half g_f1th16[Dd*FFN];
__device__ __half g_f2th16[FFN*Dd];

struct SideStream {
    cudaStream_t s = nullptr;
    cudaEvent_t fork = nullptr, wq = nullptr, join = nullptr;
    SideStream() {
        cudaStreamCreateWithFlags(&s, cudaStreamNonBlocking);
        cudaEventCreateWithFlags(&fork, cudaEventDisableTiming);
        cudaEventCreateWithFlags(&wq,   cudaEventDisableTiming);
        cudaEventCreateWithFlags(&join, cudaEventDisableTiming);
    }
};
static SideStream g_ss;

__device__ __forceinline__ float gelu_exact(float x) {
    return 0.5f * x * (1.0f + erff(x * 0.70710678118654752f));
}
__device__ __forceinline__ uint32_t packh2(float a, float b) {
    __half2 h = __floats2half2_rn(a, b);
    return *(uint32_t*)&h;
}
__device__ __forceinline__ uint32_t f2tf(float f) {
    uint32_t r;
    asm("cvt.rna.tf32.f32 %0, %1;" : "=r"(r) : "f"(f));
    return r;
}
__device__ __forceinline__ uint32_t smem_u32(const void* p) {
    uint32_t a;
    asm("{ .reg .u64 t; cvta.to.shared.u64 t, %1; cvt.u32.u64 %0, t; }" : "=r"(a) : "l"(p));
    return a;
}
__device__ __forceinline__ void cp16(uint32_t saddr, const void* g) {
    asm volatile("cp.async.ca.shared.global [%0], [%1], 16;" :: "r"(saddr), "l"(g));
}
__device__ __forceinline__ void cp_commit() { asm volatile("cp.async.commit_group;" ::: "memory"); }
__device__ __forceinline__ void cp_wait0()  { asm volatile("cp.async.wait_group 0;" ::: "memory"); }

__device__ __forceinline__ void ldsm_x4(uint32_t& r0, uint32_t& r1, uint32_t& r2, uint32_t& r3,
                                        uint32_t addr) {
    asm volatile("ldmatrix.sync.aligned.m8n8.x4.shared.b16 {%0,%1,%2,%3}, [%4];"
        : "=r"(r0), "=r"(r1), "=r"(r2), "=r"(r3) : "r"(addr));
}

__device__ __forceinline__ void mma16816h(float* c, const uint32_t* a, const uint32_t* b) {
    asm volatile("mma.sync.aligned.m16n8k16.row.col.f32.f16.f16.f32 "
        "{%0,%1,%2,%3}, {%4,%5,%6,%7}, {%8,%9}, {%0,%1,%2,%3};"
        : "+f"(c[0]), "+f"(c[1]), "+f"(c[2]), "+f"(c[3])
        : "r"(a[0]), "r"(a[1]), "r"(a[2]), "r"(a[3]), "r"(b[0]), "r"(b[1]));
}
__device__ __forceinline__ void mma1688tf(float* c, const uint32_t* a, const uint32_t* b) {
    asm volatile("mma.sync.aligned.m16n8k8.row.col.f32.tf32.tf32.f32 "
        "{%0,%1,%2,%3}, {%4,%5,%6,%7}, {%8,%9}, {%0,%1,%2,%3};"
        : "+f"(c[0]), "+f"(c[1]), "+f"(c[2]), "+f"(c[3])
        : "r"(a[0]), "r"(a[1]), "r"(a[2]), "r"(a[3]), "r"(b[0]), "r"(b[1]));
}

// ============ fp16 1-term GEMM, ldmatrix fragment loads ============
// EPI: 0 = fp32 row-major; 2 = GELU -> fp16; 3 = QKV routing (q scaled 1/8, k, v fp16).
template<int BN, int EPI>
__global__ __launch_bounds__(256)
void gemm_f16_kernel(const __half* __restrict__ Af,
                     const __half* __restrict__ Bf,
                     const float* __restrict__ bias,
                     float* __restrict__ outF, __half* __restrict__ outH,
                     __half* __restrict__ outK, __half* __restrict__ outV,
                     int M, int K, int Nc)
{
    constexpr int BM = 128;
    constexpr int WM = (BN == 128) ? 2 : 4;
    constexpr int WN = 8 / WM;
    constexpr int WTM = BM / WM;
    constexpr int WTN = BN / WN;
    constexpr int MT = WTM / 16;
    constexpr int NT = WTN / 8;
    constexpr int AS = 40;

    extern __shared__ __half smh[];
    __half* sAbase = smh;
    __half* sBbase = smh + 2 * BM * AS;

    const int t = threadIdx.x;
    const int wid = t >> 5, lane = t & 31;
    const int gid = lane >> 2, tig = lane & 3;
    const int wm = wid % WM, wn = wid / WM;
    const int mtile = blockIdx.y * BM, ntile = blockIdx.x * BN;

    float acc[MT][NT][4];
    #pragma unroll
    for (int i = 0; i < MT; i++)
        #pragma unroll
        for (int j = 0; j < NT; j++)
            #pragma unroll
            for (int r = 0; r < 4; r++) acc[i][j][r] = 0.0f;

    const int lr = t >> 2;
    const int lc = (t & 3) << 3;
    const int nch = K >> 5;

    auto load_stage = [&](int st, int k0) {
        __half* sA = sAbase + st * BM * AS;
        __half* sB = sBbase + st * BN * AS;
        #pragma unroll
        for (int rep = 0; rep < BM / 64; rep++) {
            const int rr = lr + rep * 64;
            cp16(smem_u32(sA + rr * AS + lc), Af + (size_t)(mtile + rr) * K + k0 + lc);
        }
        #pragma unroll
        for (int rep = 0; rep < BN / 64; rep++) {
            const int rr = lr + rep * 64;
            cp16(smem_u32(sB + rr * AS + lc), Bf + (size_t)(ntile + rr) * K + k0 + lc);
        }
        cp_commit();
    };

    load_stage(0, 0);

    // ldmatrix lane-derived offsets
    const int lm_row = lane & 15;             // row within m16/k-tile group
    const int lm_kh  = (lane >> 4) << 3;      // 0 or 8 (k-half for A)
    const int g4     = lane >> 3;             // 0..3 (group for B x4)
    const int b_row  = ((g4 >> 1) << 3) + (lane & 7);
    const int b_kh   = (g4 & 1) << 3;

    for (int c = 0; c < nch; c++) {
        cp_wait0();
        __syncthreads();
        if (c + 1 < nch) load_stage((c + 1) & 1, (c + 1) << 5);

        const int st = c & 1;
        const __half* sA = sAbase + st * BM * AS;
        const __half* sB = sBbase + st * BN * AS;

        #pragma unroll
        for (int kk = 0; kk < 2; kk++) {
            const int kb0 = kk * 16;
            uint32_t af[MT][4], bf[NT][2];
            #pragma unroll
            for (int i = 0; i < MT; i++) {
                const int row = wm * WTM + i * 16 + lm_row;
                ldsm_x4(af[i][0], af[i][1], af[i][2], af[i][3],
                        smem_u32(sA + row * AS + kb0 + lm_kh));
            }
            #pragma unroll
            for (int jp = 0; jp < NT / 2; jp++) {
                const int nrow = wn * WTN + jp * 16 + b_row;
                ldsm_x4(bf[2*jp][0], bf[2*jp][1], bf[2*jp+1][0], bf[2*jp+1][1],
                        smem_u32(sB + nrow * AS + kb0 + b_kh));
            }
            #pragma unroll
            for (int i = 0; i < MT; i++)
                #pragma unroll
                for (int j = 0; j < NT; j++)
                    mma16816h(acc[i][j], af[i], bf[j]);
        }
        __syncthreads();
    }

    #pragma unroll
    for (int i = 0; i < MT; i++) {
        const int r0 = mtile + wm * WTM + i * 16 + gid;
        const int r1 = r0 + 8;
        #pragma unroll
        for (int j = 0; j < NT; j++) {
            const int n = ntile + wn * WTN + j * 8 + 2 * tig;
            const float b0 = bias[n], b1 = bias[n + 1];
            float v00 = acc[i][j][0] + b0, v01 = acc[i][j][1] + b1;
            float v10 = acc[i][j][2] + b0, v11 = acc[i][j][3] + b1;
            if (EPI == 0) {
                *(float2*)&outF[(size_t)r0 * Nc + n] = make_float2(v00, v01);
                *(float2*)&outF[(size_t)r1 * Nc + n] = make_float2(v10, v11);
            } else if (EPI == 2) {
                __half2 o0 = __floats2half2_rn(gelu_exact(v00), gelu_exact(v01));
                __half2 o1 = __floats2half2_rn(gelu_exact(v10), gelu_exact(v11));
                *(__half2*)&outH[(size_t)r0 * Nc + n] = o0;
                *(__half2*)&outH[(size_t)r1 * Nc + n] = o1;
            } else { // EPI 3: QKV routing
                if (n < Dd) {
                    *(uint32_t*)&outH[(size_t)r0 * Dd + n] = packh2(v00 * 0.125f, v01 * 0.125f);
                    *(uint32_t*)&outH[(size_t)r1 * Dd + n] = packh2(v10 * 0.125f, v11 * 0.125f);
                } else if (n < 2 * Dd) {
                    const int ch = n - Dd;
                    *(uint32_t*)&outK[(size_t)r0 * Dd + ch] = packh2(v00, v01);
                    *(uint32_t*)&outK[(size_t)r1 * Dd + ch] = packh2(v10, v11);
                } else {
                    const int ch = n - 2 * Dd;
                    *(uint32_t*)&outV[(size_t)r0 * Dd + ch] = packh2(v00, v01);
                    *(uint32_t*)&outV[(size_t)r1 * Dd + ch] = packh2(v10, v11);
                }
            }
        }
    }
}

// ============ weight prep: fp32 [K,Nc] -> fp16 [Nc,K] ============
__global__ void transpose_f16_kernel(const float* __restrict__ W,
                                     __half* __restrict__ T,
                                     int K, int Nc)
{
    __shared__ float tile[32][33];
    const int n0 = blockIdx.x * 32, k0 = blockIdx.y * 32;
    const int tx = threadIdx.x, ty = threadIdx.y;
    #pragma unroll
    for (int dy = 0; dy < 32; dy += 8)
        tile[ty + dy][tx] = W[(size_t)(k0 + ty + dy) * Nc + n0 + tx];
    __syncthreads();
    #pragma unroll
    for (int dy = 0; dy < 32; dy += 8) {
        const size_t o = (size_t)(n0 + ty + dy) * K + k0 + tx;
        T[o] = __float2half_rn(tile[tx][ty + dy]);
    }
}

// QKV weight transpose + bias concat
__global__ void transpose_f16_qkv_kernel(const float* __restrict__ Wq,
                                         const float* __restrict__ Wk,
                                         const float* __restrict__ Wv,
                                         const float* __restrict__ bq,
                                         const float* __restrict__ bk,
                                         const float* __restrict__ bv,
                                         __half* __restrict__ T,
                                         float* __restrict__ bqkv)
{
    __shared__ float tile[32][33];
    const int z = blockIdx.z;
    const float* W = (z == 0) ? Wq : (z == 1) ? Wk : Wv;
    const size_t woff = (size_t)z * Dd * Dd;
    const int n0 = blockIdx.x * 32, k0 = blockIdx.y * 32;
    const int tx = threadIdx.x, ty = threadIdx.y;
    if (blockIdx.y == 0 && ty == 0) {
        const float* bsrc = (z == 0) ? bq : (z == 1) ? bk : bv;
        bqkv[z * Dd + n0 + tx] = bsrc[n0 + tx];
    }
    #pragma unroll
    for (int dy = 0; dy < 32; dy += 8)
        tile[ty + dy][tx] = W[(size_t)(k0 + ty + dy) * Dd + n0 + tx];
    __syncthreads();
    #pragma unroll
    for (int dy = 0; dy < 32; dy += 8) {
        const size_t o = woff + (size_t)(n0 + ty + dy) * Dd + k0 + tx;
        T[o] = __float2half_rn(tile[tx][ty + dy]);
    }
}

// ============ fp32 -> fp16 elementwise ============
__global__ void to_f16_kernel(const float* __restrict__ in, __half* __restrict__ out)
{
    const int i = blockIdx.x * 256 + threadIdx.x;
    float4 v = ((const float4*)in)[i];
    ((uint32_t*)out)[i * 2 + 0] = packh2(v.x, v.y);
    ((uint32_t*)out)[i * 2 + 1] = packh2(v.z, v.w);
}

// ============ V fp16 row-major -> V^T fp16 [b,ch,tok] ============
__global__ void vT16_kernel(const __half* __restrict__ v16,
                            __half* __restrict__ vt16)
{
    __shared__ __half tile[32][40];
    const int tok0 = blockIdx.x * 32, ch0 = blockIdx.y * 32, b = blockIdx.z;
    const int tx = threadIdx.x, ty = threadIdx.y;
    #pragma unroll
    for (int dy = 0; dy < 32; dy += 8)
        tile[ty + dy][tx] = v16[((size_t)(b * Nn + tok0 + ty + dy)) * Dd + ch0 + tx];
    __syncthreads();
    #pragma unroll
    for (int dy = 0; dy < 32; dy += 8) {
        const size_t o = ((size_t)(b * Dd + ch0 + ty + dy)) * Nn + tok0 + tx;
        vt16[o] = tile[tx][ty + dy];
    }
}

// ============ RPE: tf32 layer1 -> relu -> fp16 layer2 (tensor) ============
__global__ __launch_bounds__(256)
void rpe_kernel(const float* __restrict__ rel_pos,
                const float* __restrict__ R1, const float* __restrict__ rb1,
                const float* __restrict__ R2, const float* __restrict__ rb2,
                __half* __restrict__ rpe)
{
    __shared__ __half sh_out[8][128];

    const int j0 = blockIdx.x * 128;
    const int i  = blockIdx.y;
    const int b  = blockIdx.z;
    const int t  = threadIdx.x;
    const int w = t >> 5, lane = t & 31;
    const int gid = lane >> 2, tig = lane & 3;
    const int jw = w * 16;

    uint32_t b1f[8];
    #pragma unroll
    for (int ut = 0; ut < 8; ut++) b1f[ut] = f2tf(R1[tig * 64 + ut * 8 + gid]);

    const float* rp = rel_pos + ((size_t)(b * Nn + i) * Nn + j0 + jw) * 4;
    uint32_t a1f[4];
    a1f[0] = f2tf(rp[gid * 4 + tig]);
    a1f[1] = f2tf(rp[(gid + 8) * 4 + tig]);
    a1f[2] = 0u;
    a1f[3] = 0u;

    float c1[8][4];
    #pragma unroll
    for (int ut = 0; ut < 8; ut++) {
        c1[ut][0] = 0.f; c1[ut][1] = 0.f; c1[ut][2] = 0.f; c1[ut][3] = 0.f;
        uint32_t bb[2] = { b1f[ut], 0u };
        mma1688tf(c1[ut], a1f, bb);
        const float r0 = rb1[ut * 8 + 2 * tig], r1 = rb1[ut * 8 + 2 * tig + 1];
        c1[ut][0] = fmaxf(c1[ut][0] + r0, 0.f);
        c1[ut][1] = fmaxf(c1[ut][1] + r1, 0.f);
        c1[ut][2] = fmaxf(c1[ut][2] + r0, 0.f);
        c1[ut][3] = fmaxf(c1[ut][3] + r1, 0.f);
    }

    float c2[4] = {0.f, 0.f, 0.f, 0.f};
    #pragma unroll
    for (int ks = 0; ks < 4; ks++) {
        uint32_t a2[4];
        a2[0] = packh2(c1[2 * ks][0],     c1[2 * ks][1]);
        a2[1] = packh2(c1[2 * ks][2],     c1[2 * ks][3]);
        a2[2] = packh2(c1[2 * ks + 1][0], c1[2 * ks + 1][1]);
        a2[3] = packh2(c1[2 * ks + 1][2], c1[2 * ks + 1][3]);
        uint32_t b2[2];
        b2[0] = packh2(R2[(16 * ks + 2 * tig) * 8 + gid],     R2[(16 * ks + 2 * tig + 1) * 8 + gid]);
        b2[1] = packh2(R2[(16 * ks + 8 + 2 * tig) * 8 + gid], R2[(16 * ks + 9 + 2 * tig) * 8 + gid]);
        mma16816h(c2, a2, b2);
    }
    const float rbA = rb2[2 * tig], rbB = rb2[2 * tig + 1];
    sh_out[2 * tig    ][jw + gid]     = __float2half(c2[0] + rbA);
    sh_out[2 * tig + 1][jw + gid]     = __float2half(c2[1] + rbB);
    sh_out[2 * tig    ][jw + gid + 8] = __float2half(c2[2] + rbA);
    sh_out[2 * tig + 1][jw + gid + 8] = __float2half(c2[3] + rbB);
    __syncthreads();

    const uint32_t* src = (const uint32_t*)sh_out;
    #pragma unroll
    for (int u = t; u < 512; u += 256) {
        const int hh = u >> 6, col = u & 63;
        ((uint32_t*)(rpe + (((size_t)(b * Hh + hh) * Nn + i) * Nn + j0)))[col] = src[hh * 64 + col];
    }
}

// ============ attention: R13 shape + ldmatrix K/V frags ============
__global__ __launch_bounds__(128)
void attn_mma_kernel(const __half* __restrict__ q16,
                     const __half* __restrict__ k16,
                     const __half* __restrict__ vt16,
                     const __half* __restrict__ rpe,
                     float* __restrict__ pacc, float* __restrict__ pm, float* __restrict__ pl)
{
    __shared__ __half sK[2][64 * 72];
    __shared__ __half sV[2][64 * 72];

    const int it = blockIdx.x;
    const int b  = blockIdx.y;
    const int h  = blockIdx.z >> 1;
    const int sp = blockIdx.z & 1;
    const int t = threadIdx.x;
    const int w = t >> 5, lane = t & 31;
    const int gid = lane >> 2, tig = lane & 3;
    const int i0 = it * 64 + w * 16;
    const int jbeg = sp * NSPLIT;
    const int njt = NSPLIT / 64;

    // ldmatrix lane offsets for B frags (pairs x k-halves)
    const int g4    = lane >> 3;
    const int b_row = ((g4 >> 1) << 3) + (lane & 7);
    const int b_kh  = (g4 & 1) << 3;

    // preload q A-frags (fp16) for this warp's 16 rows
    uint32_t aq[4][4];
    {
        const __half* qb = q16 + (size_t)(b * Nn) * Dd + h * 64;
        #pragma unroll
        for (int ks = 0; ks < 4; ks++) {
            const int kb = ks * 16 + 2 * tig;
            const __half* p0 = qb + (size_t)(i0 + gid) * Dd + kb;
            const __half* p1 = qb + (size_t)(i0 + gid + 8) * Dd + kb;
            aq[ks][0] = *(const uint32_t*)p0;
            aq[ks][1] = *(const uint32_t*)p1;
            aq[ks][2] = *(const uint32_t*)(p0 + 8);
            aq[ks][3] = *(const uint32_t*)(p1 + 8);
        }
    }

    float acc[8][4];
    #pragma unroll
    for (int nf = 0; nf < 8; nf++)
        #pragma unroll
        for (int r = 0; r < 4; r++) acc[nf][r] = 0.0f;
    float m0 = -1e30f, m1 = -1e30f, l0 = 0.0f, l1 = 0.0f;

    auto stage_tile = [&](int st, int j0) {
        #pragma unroll
        for (int u = t; u < 512; u += 128) {
            const int r = u >> 3, c8 = (u & 7) << 3;
            cp16(smem_u32(&sK[st][r * 72 + c8]),
                 k16 + (size_t)(b * Nn + j0 + r) * Dd + h * 64 + c8);
        }
        #pragma unroll
        for (int u = t; u < 512; u += 128) {
            const int r = u >> 3, c8 = (u & 7) << 3;
            cp16(smem_u32(&sV[st][r * 72 + c8]),
                 vt16 + (size_t)(b * Dd + h * 64 + r) * Nn + j0 + c8);
        }
        cp_commit();
    };

    stage_tile(0, jbeg);

    for (int jt = 0; jt < njt; jt++) {
        const int j0 = jbeg + jt * 64;
        cp_wait0();
        __syncthreads();
        if (jt + 1 < njt) stage_tile((jt + 1) & 1, j0 + 64);

        const __half* sKt = sK[jt & 1];
        const __half* sVt = sV[jt & 1];

        // scores via ldmatrix B frags: jf pairs x ks
        float s[8][4];
        #pragma unroll
        for (int p = 0; p < 4; p++) {
            float* sE = s[2 * p];
            float* sO = s[2 * p + 1];
            sE[0] = 0.f; sE[1] = 0.f; sE[2] = 0.f; sE[3] = 0.f;
            sO[0] = 0.f; sO[1] = 0.f; sO[2] = 0.f; sO[3] = 0.f;
            #pragma unroll
            for (int ks = 0; ks < 4; ks++) {
                uint32_t r0, r1, r2, r3;
                ldsm_x4(r0, r1, r2, r3,
                        smem_u32(sKt + (p * 16 + b_row) * 72 + ks * 16 + b_kh));
                uint32_t bA[2] = { r0, r1 }, bB[2] = { r2, r3 };
                mma16816h(sE, aq[ks], bA);
                mma16816h(sO, aq[ks], bB);
            }
        }
        // add rpe
        {
            const uint32_t* rp32 = (const uint32_t*)rpe;
            const size_t row0 = ((size_t)(b * Hh + h) * Nn + i0 + gid) * 512 + (j0 >> 1) + tig;
            const size_t row1 = row0 + 8 * 512;
            #pragma unroll
            for (int jf = 0; jf < 8; jf++) {
                uint32_t u0 = rp32[row0 + jf * 4];
                uint32_t u1 = rp32[row1 + jf * 4];
                float2 f0 = __half22float2(*(const __half2*)&u0);
                float2 f1 = __half22float2(*(const __half2*)&u1);
                s[jf][0] += f0.x; s[jf][1] += f0.y;
                s[jf][2] += f1.x; s[jf][3] += f1.y;
            }
        }

        // online softmax
        float mx0 = -1e30f, mx1 = -1e30f;
        #pragma unroll
        for (int jf = 0; jf < 8; jf++) {
            mx0 = fmaxf(mx0, fmaxf(s[jf][0], s[jf][1]));
            mx1 = fmaxf(mx1, fmaxf(s[jf][2], s[jf][3]));
        }
        mx0 = fmaxf(mx0, __shfl_xor_sync(0xffffffffu, mx0, 1));
        mx0 = fmaxf(mx0, __shfl_xor_sync(0xffffffffu, mx0, 2));
        mx1 = fmaxf(mx1, __shfl_xor_sync(0xffffffffu, mx1, 1));
        mx1 = fmaxf(mx1, __shfl_xor_sync(0xffffffffu, mx1, 2));
        const float M0 = fmaxf(m0, mx0), M1 = fmaxf(m1, mx1);
        const float sc0 = __expf(m0 - M0), sc1 = __expf(m1 - M1);
        float ls0 = 0.0f, ls1 = 0.0f;
        #pragma unroll
        for (int jf = 0; jf < 8; jf++) {
            s[jf][0] = __expf(s[jf][0] - M0); ls0 += s[jf][0];
            s[jf][1] = __expf(s[jf][1] - M0); ls0 += s[jf][1];
            s[jf][2] = __expf(s[jf][2] - M1); ls1 += s[jf][2];
            s[jf][3] = __expf(s[jf][3] - M1); ls1 += s[jf][3];
        }
        ls0 += __shfl_xor_sync(0xffffffffu, ls0, 1);
        ls0 += __shfl_xor_sync(0xffffffffu, ls0, 2);
        ls1 += __shfl_xor_sync(0xffffffffu, ls1, 1);
        ls1 += __shfl_xor_sync(0xffffffffu, ls1, 2);
        l0 = l0 * sc0 + ls0;
        l1 = l1 * sc1 + ls1;
        m0 = M0; m1 = M1;
        #pragma unroll
        for (int nf = 0; nf < 8; nf++) {
            acc[nf][0] *= sc0; acc[nf][1] *= sc0;
            acc[nf][2] *= sc1; acc[nf][3] *= sc1;
        }

        // P -> fp16 A-frags
        uint32_t ph[4][4];
        #pragma unroll
        for (int kf = 0; kf < 4; kf++) {
            const int jE = 2 * kf, jO = 2 * kf + 1;
            ph[kf][0] = packh2(s[jE][0], s[jE][1]);
            ph[kf][1] = packh2(s[jE][2], s[jE][3]);
            ph[kf][2] = packh2(s[jO][0], s[jO][1]);
            ph[kf][3] = packh2(s[jO][2], s[jO][3]);
        }

        // AV via ldmatrix B frags: nf pairs x kf
        #pragma unroll
        for (int p = 0; p < 4; p++) {
            float* aE = acc[2 * p];
            float* aO = acc[2 * p + 1];
            #pragma unroll
            for (int kf = 0; kf < 4; kf++) {
                uint32_t r0, r1, r2, r3;
                ldsm_x4(r0, r1, r2, r3,
                        smem_u32(sVt + (p * 16 + b_row) * 72 + kf * 16 + b_kh));
                uint32_t bA[2] = { r0, r1 }, bB[2] = { r2, r3 };
                mma16816h(aE, ph[kf], bA);
                mma16816h(aO, ph[kf], bB);
            }
        }
        __syncthreads();
    }

    float* pab = pacc + (size_t)sp * (Bb * Nn * Dd) + (size_t)b * (Nn * Dd);
    #pragma unroll
    for (int nf = 0; nf < 8; nf++) {
        const int ch = h * 64 + nf * 8 + 2 * tig;
        *(float2*)&pab[(size_t)(i0 + gid) * Dd + ch]     = make_float2(acc[nf][0], acc[nf][1]);
        *(float2*)&pab[(size_t)(i0 + gid + 8) * Dd + ch] = make_float2(acc[nf][2], acc[nf][3]);
    }
    if (tig == 0) {
        const size_t ix0 = (((size_t)sp * Bb + b) * Nn + i0 + gid) * Hh + h;
        const size_t ix1 = (((size_t)sp * Bb + b) * Nn + i0 + gid + 8) * Hh + h;
        pm[ix0] = m0; pl[ix0] = l0;
        pm[ix1] = m1; pl[ix1] = l1;
    }
}

// ---------------- combine partials -> ao fp16 ----------------
__global__ void attn_combine_kernel(const float* __restrict__ pacc,
                                    const float* __restrict__ pm,
                                    const float* __restrict__ pl,
                                    __half* __restrict__ ao16)
{
    const int i = blockIdx.x;
    const int b = blockIdx.y;
    const int t = threadIdx.x;
    __shared__ float sh_w[SPL][Hh];
    __shared__ float sh_invL[Hh];

    if (t < Hh) {
        float m[SPL], l[SPL];
        float M = -1e30f;
        #pragma unroll
        for (int s = 0; s < SPL; s++) {
            size_t idx = (((size_t)s * Bb + b) * Nn + i) * Hh + t;
            m[s] = pm[idx]; l[s] = pl[idx];
            M = fmaxf(M, m[s]);
        }
        float L = 0.0f;
        #pragma unroll
        for (int s = 0; s < SPL; s++) {
            float w = __expf(m[s] - M);
            sh_w[s][t] = w;
            L = fmaf(l[s], w, L);
        }
        sh_invL[t] = 1.0f / L;
    }
    __syncthreads();

    const int e0 = t, e1 = t + 256;
    const int he0 = t >> 6, he1 = he0 + 4;
    const size_t row = ((size_t)(b * Nn) + i) * Dd;
    float a0 = 0.0f, a1 = 0.0f;
    #pragma unroll
    for (int s = 0; s < SPL; s++) {
        const float* pab = pacc + (size_t)s * (Bb * Nn * Dd);
        a0 = fmaf(pab[row + e0], sh_w[s][he0], a0);
        a1 = fmaf(pab[row + e1], sh_w[s][he1], a1);
    }
    ao16[row + e0] = __float2half(a0 * sh_invL[he0]);
    ao16[row + e1] = __float2half(a1 * sh_invL[he1]);
}

// ---------------- residual + LayerNorm ----------------
template<int H16>
__global__ void ln_kernel(const float* __restrict__ x, const float* __restrict__ add,
                          const float* __restrict__ g, const float* __restrict__ bet,
                          float* __restrict__ out, __half* __restrict__ outH)
{
    const int row = blockIdx.x;
    const int t = threadIdx.x;
    const size_t base = (size_t)row * Dd;
    float v0 = x[base + t]       + add[base + t];
    float v1 = x[base + t + 256] + add[base + t + 256];
    float s  = v0 + v1;
    float s2 = v0 * v0 + v1 * v1;
    #pragma unroll
    for (int o = 16; o > 0; o >>= 1) {
        s  += __shfl_xor_sync(0xffffffffu, s,  o);
        s2 += __shfl_xor_sync(0xffffffffu, s2, o);
    }
    __shared__ float ws[8], ws2[8];
    __shared__ float mu_s, rs_s;
    if ((t & 31) == 0) { ws[t >> 5] = s; ws2[t >> 5] = s2; }
    __syncthreads();
    if (t == 0) {
        float S = 0.0f, S2 = 0.0f;
        #pragma unroll
        for (int w = 0; w < 8; w++) { S += ws[w]; S2 += ws2[w]; }
        float mu = S * (1.0f / 512.0f);
        float var = S2 * (1.0f / 512.0f) - mu * mu;
        mu_s = mu;
        rs_s = rsqrtf(var + 1e-5f);
    }
    __syncthreads();
    float o0 = (v0 - mu_s) * rs_s * g[t]       + bet[t];
    float o1 = (v1 - mu_s) * rs_s * g[t + 256] + bet[t + 256];
    out[base + t]       = o0;
    out[base + t + 256] = o1;
    if (H16) {
        outH[base + t]       = __float2half(o0);
        outH[base + t + 256] = __float2half(o1);
    }
}

// ---------------- launch ----------------
extern "C" void kernel_launch(void* const* d_in, const int* in_sizes, int n_in,
                              void* d_out, int out_size)
{
    (void)in_sizes; (void)n_in; (void)out_size;
    const float* x       = (const float*)d_in[0];
    const float* rel_pos = (const float*)d_in[1];
    const float* Wq = (const float*)d_in[2];  const float* bq = (const float*)d_in[3];
    const float* Wk = (const float*)d_in[4];  const float* bk = (const float*)d_in[5];
    const float* Wv = (const float*)d_in[6];  const float* bv = (const float*)d_in[7];
    const float* Wo = (const float*)d_in[8];  const float* bo = (const float*)d_in[9];
    const float* R1 = (const float*)d_in[10]; const float* rb1 = (const float*)d_in[11];
    const float* R2 = (const float*)d_in[12]; const float* rb2 = (const float*)d_in[13];
    const float* g1 = (const float*)d_in[14]; const float* b1 = (const float*)d_in[15];
    const float* g2 = (const float*)d_in[16]; const float* b2 = (const float*)d_in[17];
    const float* F1 = (const float*)d_in[18]; const float* fb1 = (const float*)d_in[19];
    const float* F2 = (const float*)d_in[20]; const float* fb2 = (const float*)d_in[21];
    float* outp = (float*)d_out;

    float *wo, *x1, *f2, *pacc, *pm, *pl, *bqkv;
    cudaGetSymbolAddress((void**)&wo,   g_wo);
    cudaGetSymbolAddress((void**)&x1,   g_x1);
    cudaGetSymbolAddress((void**)&f2,   g_f2);
    cudaGetSymbolAddress((void**)&pacc, g_pacc);
    cudaGetSymbolAddress((void**)&pm,   g_pm);
    cudaGetSymbolAddress((void**)&pl,   g_pl);
    cudaGetSymbolAddress((void**)&bqkv, g_bqkv);

    __half *x16, *q16, *k16, *v16, *vt16, *ao16, *x116, *h16;
    __half *wqkvt16, *woth16, *f1th16, *f2th16, *rpe;
    cudaGetSymbolAddress((void**)&x16,  g_x16);
    cudaGetSymbolAddress((void**)&q16,  g_q16);
    cudaGetSymbolAddress((void**)&k16,  g_k16);
    cudaGetSymbolAddress((void**)&v16,  g_v16);
    cudaGetSymbolAddress((void**)&vt16, g_vt16);
    cudaGetSymbolAddress((void**)&ao16, g_ao16);
    cudaGetSymbolAddress((void**)&x116, g_x116);
    cudaGetSymbolAddress((void**)&h16,  g_h16);
    cudaGetSymbolAddress((void**)&wqkvt16, g_wqkvt16);
    cudaGetSymbolAddress((void**)&woth16, g_woth16);
    cudaGetSymbolAddress((void**)&f1th16, g_f1th16);
    cudaGetSymbolAddress((void**)&f2th16, g_f2th16);
    cudaGetSymbolAddress((void**)&rpe,  g_rpe);

    const int M = Bb * Nn;
    dim3 tb(32, 8);

    constexpr int AS = 40;
    const int SMEM_F64  = (2 * 128 * AS + 2 * 64 * AS) * (int)sizeof(__half);
    const int SMEM_F128 = (2 * 128 * AS + 2 * 128 * AS) * (int)sizeof(__half);
    cudaFuncSetAttribute(gemm_f16_kernel<64,0>,  cudaFuncAttributeMaxDynamicSharedMemorySize, SMEM_F64);
    cudaFuncSetAttribute(gemm_f16_kernel<128,2>, cudaFuncAttributeMaxDynamicSharedMemorySize, SMEM_F128);
    cudaFuncSetAttribute(gemm_f16_kernel<128,3>, cudaFuncAttributeMaxDynamicSharedMemorySize, SMEM_F128);

    // ---- fork: side stream: QKV weight transpose first (own event), then rpe + Wo/FFN transposes
    cudaEventRecord(g_ss.fork, 0);
    cudaStreamWaitEvent(g_ss.s, g_ss.fork, 0);
    transpose_f16_qkv_kernel<<<dim3(16, 16, 3), tb, 0, g_ss.s>>>(Wq, Wk, Wv, bq, bk, bv, wqkvt16, bqkv);
    cudaEventRecord(g_ss.wq, g_ss.s);
    rpe_kernel<<<dim3(Nn / 128, Nn, Bb), 256, 0, g_ss.s>>>(rel_pos, R1, rb1, R2, rb2, rpe);
    transpose_f16_kernel<<<dim3(16, 16), tb, 0, g_ss.s>>>(Wo, woth16, Dd, Dd);
    transpose_f16_kernel<<<dim3(64, 16), tb, 0, g_ss.s>>>(F1, f1th16, Dd, FFN);
    transpose_f16_kernel<<<dim3(16, 64), tb, 0, g_ss.s>>>(F2, f2th16, FFN, Dd);
    cudaEventRecord(g_ss.join, g_ss.s);

    // ---- main stream ----
    to_f16_kernel<<<(M * Dd / 4) / 256, 256>>>(x, x16);
    cudaStreamWaitEvent(0, g_ss.wq, 0);

    gemm_f16_kernel<128,3><<<dim3(3 * Dd / 128, M / 128), 256, SMEM_F128>>>(
        x16, wqkvt16, bqkv, nullptr, q16, k16, v16, M, Dd, 3 * Dd);
    vT16_kernel<<<dim3(Nn / 32, Dd / 32, Bb), tb>>>(v16, vt16);

    cudaStreamWaitEvent(0, g_ss.join, 0);

    attn_mma_kernel<<<dim3(Nn / 64, Bb, Hh * SPL), 128>>>(q16, k16, vt16, rpe, pacc, pm, pl);
    attn_combine_kernel<<<dim3(Nn, Bb), 256>>>(pacc, pm, pl, ao16);

    gemm_f16_kernel<64,0><<<dim3(Dd / 64, M / 128), 256, SMEM_F64>>>(
        ao16, woth16, bo, wo, nullptr, nullptr, nullptr, M, Dd, Dd);
    ln_kernel<1><<<M, 256>>>(x, wo, g1, b1, x1, x116);

    gemm_f16_kernel<128,2><<<dim3(FFN / 128, M / 128), 256, SMEM_F128>>>(
        x116, f1th16, fb1, nullptr, h16, nullptr, nullptr, M, Dd, FFN);
    gemm_f16_kernel<64,0><<<dim3(Dd / 64, M / 128), 256, SMEM_F64>>>(
        h16, f2th16, fb2, f2, nullptr, nullptr, nullptr, M, FFN, Dd);
    ln_kernel<0><<<M, 256>>>(x1, f2, g2, b2, outp, nullptr);
}

// round 17
// speedup vs baseline: 1.1500x; 1.0329x over previous
#include <cuda_runtime.h>
#include <cuda_bf16.h>
#include <cuda_fp16.h>
#include <math.h>
#include <stdint.h>

#define Bb 2
#define Nn 1024
#define Dd 512
#define Hh 8
#define HD 64
#define FFN 2048
#define SPL 2
#define NSPLIT (Nn / SPL)

// ---------------- scratch ----------------
__device__ float g_wo [Bb*Nn*Dd];
__device__ float g_x1 [Bb*Nn*Dd];
__device__ float g_f2 [Bb*Nn*Dd];
__device__ __half g_pacc16[SPL*Bb*Nn*Dd];
__device__ float g_pm[SPL*Bb*Nn*Hh];
__device__ float g_pl[SPL*Bb*Nn*Hh];
__device__ float g_bqkv[3*Dd];

__device__ __half g_x16 [Bb*Nn*Dd];
__device__ __half g_q16 [Bb*Nn*Dd];          // scaled by 1/8
__device__ __half g_k16 [Bb*Nn*Dd];
__device__ __half g_v16 [Bb*Nn*Dd];          // row-major
__device__ __half g_vt16[Bb*Dd*Nn];          // transposed [b,ch,tok]
__device__ __half g_ao16[Bb*Nn*Dd];
__device__ __half g_x116[Bb*Nn*Dd];
__device__ __half g_h16 [Bb*Nn*FFN];
__device__ __half g_rpe[Bb*Hh*Nn*Nn];
__device__ __half g_wqkvt16[3*Dd*Dd];
__device__ __half g_woth16[Dd*Dd];
__device__ __half g_f1th16[Dd*FFN];
__device__ __half g_f2th16[FFN*Dd];

struct SideStream {
    cudaStream_t s = nullptr;
    cudaEvent_t fork = nullptr, wq = nullptr, join = nullptr;
    SideStream() {
        cudaStreamCreateWithFlags(&s, cudaStreamNonBlocking);
        cudaEventCreateWithFlags(&fork, cudaEventDisableTiming);
        cudaEventCreateWithFlags(&wq,   cudaEventDisableTiming);
        cudaEventCreateWithFlags(&join, cudaEventDisableTiming);
    }
};
static SideStream g_ss;

__device__ __forceinline__ float gelu_exact(float x) {
    return 0.5f * x * (1.0f + erff(x * 0.70710678118654752f));
}
__device__ __forceinline__ uint32_t packh2(float a, float b) {
    __half2 h = __floats2half2_rn(a, b);
    return *(uint32_t*)&h;
}
__device__ __forceinline__ uint32_t f2tf(float f) {
    uint32_t r;
    asm("cvt.rna.tf32.f32 %0, %1;" : "=r"(r) : "f"(f));
    return r;
}
__device__ __forceinline__ uint32_t smem_u32(const void* p) {
    uint32_t a;
    asm("{ .reg .u64 t; cvta.to.shared.u64 t, %1; cvt.u32.u64 %0, t; }" : "=r"(a) : "l"(p));
    return a;
}
__device__ __forceinline__ void cp16(uint32_t saddr, const void* g) {
    asm volatile("cp.async.ca.shared.global [%0], [%1], 16;" :: "r"(saddr), "l"(g));
}
__device__ __forceinline__ void cp_commit() { asm volatile("cp.async.commit_group;" ::: "memory"); }
__device__ __forceinline__ void cp_wait0()  { asm volatile("cp.async.wait_group 0;" ::: "memory"); }

__device__ __forceinline__ void ldsm_x4(uint32_t& r0, uint32_t& r1, uint32_t& r2, uint32_t& r3,
                                        uint32_t addr) {
    asm volatile("ldmatrix.sync.aligned.m8n8.x4.shared.b16 {%0,%1,%2,%3}, [%4];"
        : "=r"(r0), "=r"(r1), "=r"(r2), "=r"(r3) : "r"(addr));
}

__device__ __forceinline__ void mma16816h(float* c, const uint32_t* a, const uint32_t* b) {
    asm volatile("mma.sync.aligned.m16n8k16.row.col.f32.f16.f16.f32 "
        "{%0,%1,%2,%3}, {%4,%5,%6,%7}, {%8,%9}, {%0,%1,%2,%3};"
        : "+f"(c[0]), "+f"(c[1]), "+f"(c[2]), "+f"(c[3])
        : "r"(a[0]), "r"(a[1]), "r"(a[2]), "r"(a[3]), "r"(b[0]), "r"(b[1]));
}
__device__ __forceinline__ void mma1688tf(float* c, const uint32_t* a, const uint32_t* b) {
    asm volatile("mma.sync.aligned.m16n8k8.row.col.f32.tf32.tf32.f32 "
        "{%0,%1,%2,%3}, {%4,%5,%6,%7}, {%8,%9}, {%0,%1,%2,%3};"
        : "+f"(c[0]), "+f"(c[1]), "+f"(c[2]), "+f"(c[3])
        : "r"(a[0]), "r"(a[1]), "r"(a[2]), "r"(a[3]), "r"(b[0]), "r"(b[1]));
}

// ============ fp16 1-term GEMM, ldmatrix fragment loads, BM/BN tiled ============
// EPI: 0 = fp32 row-major; 2 = GELU -> fp16; 3 = QKV routing (q scaled 1/8, k, v fp16).
template<int BM, int BN, int EPI>
__global__ __launch_bounds__(256)
void gemm_f16_kernel(const __half* __restrict__ Af,
                     const __half* __restrict__ Bf,
                     const float* __restrict__ bias,
                     float* __restrict__ outF, __half* __restrict__ outH,
                     __half* __restrict__ outK, __half* __restrict__ outV,
                     int M, int K, int Nc)
{
    constexpr int WM = (BM == 64) ? 2 : ((BN == 128) ? 2 : 4);
    constexpr int WN = 8 / WM;
    constexpr int WTM = BM / WM;
    constexpr int WTN = BN / WN;
    constexpr int MT = WTM / 16;
    constexpr int NT = WTN / 8;
    constexpr int AS = 40;

    extern __shared__ __half smh[];
    __half* sAbase = smh;
    __half* sBbase = smh + 2 * BM * AS;

    const int t = threadIdx.x;
    const int wid = t >> 5, lane = t & 31;
    const int gid = lane >> 2, tig = lane & 3;
    const int wm = wid % WM, wn = wid / WM;
    const int mtile = blockIdx.y * BM, ntile = blockIdx.x * BN;

    float acc[MT][NT][4];
    #pragma unroll
    for (int i = 0; i < MT; i++)
        #pragma unroll
        for (int j = 0; j < NT; j++)
            #pragma unroll
            for (int r = 0; r < 4; r++) acc[i][j][r] = 0.0f;

    const int lr = t >> 2;
    const int lc = (t & 3) << 3;
    const int nch = K >> 5;

    auto load_stage = [&](int st, int k0) {
        __half* sA = sAbase + st * BM * AS;
        __half* sB = sBbase + st * BN * AS;
        #pragma unroll
        for (int rep = 0; rep < BM / 64; rep++) {
            const int rr = lr + rep * 64;
            cp16(smem_u32(sA + rr * AS + lc), Af + (size_t)(mtile + rr) * K + k0 + lc);
        }
        #pragma unroll
        for (int rep = 0; rep < BN / 64; rep++) {
            const int rr = lr + rep * 64;
            cp16(smem_u32(sB + rr * AS + lc), Bf + (size_t)(ntile + rr) * K + k0 + lc);
        }
        cp_commit();
    };

    load_stage(0, 0);

    // ldmatrix lane-derived offsets
    const int lm_row = lane & 15;
    const int lm_kh  = (lane >> 4) << 3;
    const int g4     = lane >> 3;
    const int b_row  = ((g4 >> 1) << 3) + (lane & 7);
    const int b_kh   = (g4 & 1) << 3;

    for (int c = 0; c < nch; c++) {
        cp_wait0();
        __syncthreads();
        if (c + 1 < nch) load_stage((c + 1) & 1, (c + 1) << 5);

        const int st = c & 1;
        const __half* sA = sAbase + st * BM * AS;
        const __half* sB = sBbase + st * BN * AS;

        #pragma unroll
        for (int kk = 0; kk < 2; kk++) {
            const int kb0 = kk * 16;
            uint32_t af[MT][4], bf[NT][2];
            #pragma unroll
            for (int i = 0; i < MT; i++) {
                const int row = wm * WTM + i * 16 + lm_row;
                ldsm_x4(af[i][0], af[i][1], af[i][2], af[i][3],
                        smem_u32(sA + row * AS + kb0 + lm_kh));
            }
            #pragma unroll
            for (int jp = 0; jp < NT / 2; jp++) {
                const int nrow = wn * WTN + jp * 16 + b_row;
                ldsm_x4(bf[2*jp][0], bf[2*jp][1], bf[2*jp+1][0], bf[2*jp+1][1],
                        smem_u32(sB + nrow * AS + kb0 + b_kh));
            }
            #pragma unroll
            for (int i = 0; i < MT; i++)
                #pragma unroll
                for (int j = 0; j < NT; j++)
                    mma16816h(acc[i][j], af[i], bf[j]);
        }
        __syncthreads();
    }

    #pragma unroll
    for (int i = 0; i < MT; i++) {
        const int r0 = mtile + wm * WTM + i * 16 + gid;
        const int r1 = r0 + 8;
        #pragma unroll
        for (int j = 0; j < NT; j++) {
            const int n = ntile + wn * WTN + j * 8 + 2 * tig;
            const float b0 = bias[n], b1 = bias[n + 1];
            float v00 = acc[i][j][0] + b0, v01 = acc[i][j][1] + b1;
            float v10 = acc[i][j][2] + b0, v11 = acc[i][j][3] + b1;
            if (EPI == 0) {
                *(float2*)&outF[(size_t)r0 * Nc + n] = make_float2(v00, v01);
                *(float2*)&outF[(size_t)r1 * Nc + n] = make_float2(v10, v11);
            } else if (EPI == 2) {
                __half2 o0 = __floats2half2_rn(gelu_exact(v00), gelu_exact(v01));
                __half2 o1 = __floats2half2_rn(gelu_exact(v10), gelu_exact(v11));
                *(__half2*)&outH[(size_t)r0 * Nc + n] = o0;
                *(__half2*)&outH[(size_t)r1 * Nc + n] = o1;
            } else { // EPI 3: QKV routing
                if (n < Dd) {
                    *(uint32_t*)&outH[(size_t)r0 * Dd + n] = packh2(v00 * 0.125f, v01 * 0.125f);
                    *(uint32_t*)&outH[(size_t)r1 * Dd + n] = packh2(v10 * 0.125f, v11 * 0.125f);
                } else if (n < 2 * Dd) {
                    const int ch = n - Dd;
                    *(uint32_t*)&outK[(size_t)r0 * Dd + ch] = packh2(v00, v01);
                    *(uint32_t*)&outK[(size_t)r1 * Dd + ch] = packh2(v10, v11);
                } else {
                    const int ch = n - 2 * Dd;
                    *(uint32_t*)&outV[(size_t)r0 * Dd + ch] = packh2(v00, v01);
                    *(uint32_t*)&outV[(size_t)r1 * Dd + ch] = packh2(v10, v11);
                }
            }
        }
    }
}

// ============ weight prep: fp32 [K,Nc] -> fp16 [Nc,K] ============
__global__ void transpose_f16_kernel(const float* __restrict__ W,
                                     __half* __restrict__ T,
                                     int K, int Nc)
{
    __shared__ float tile[32][33];
    const int n0 = blockIdx.x * 32, k0 = blockIdx.y * 32;
    const int tx = threadIdx.x, ty = threadIdx.y;
    #pragma unroll
    for (int dy = 0; dy < 32; dy += 8)
        tile[ty + dy][tx] = W[(size_t)(k0 + ty + dy) * Nc + n0 + tx];
    __syncthreads();
    #pragma unroll
    for (int dy = 0; dy < 32; dy += 8) {
        const size_t o = (size_t)(n0 + ty + dy) * K + k0 + tx;
        T[o] = __float2half_rn(tile[tx][ty + dy]);
    }
}

// QKV weight transpose + bias concat
__global__ void transpose_f16_qkv_kernel(const float* __restrict__ Wq,
                                         const float* __restrict__ Wk,
                                         const float* __restrict__ Wv,
                                         const float* __restrict__ bq,
                                         const float* __restrict__ bk,
                                         const float* __restrict__ bv,
                                         __half* __restrict__ T,
                                         float* __restrict__ bqkv)
{
    __shared__ float tile[32][33];
    const int z = blockIdx.z;
    const float* W = (z == 0) ? Wq : (z == 1) ? Wk : Wv;
    const size_t woff = (size_t)z * Dd * Dd;
    const int n0 = blockIdx.x * 32, k0 = blockIdx.y * 32;
    const int tx = threadIdx.x, ty = threadIdx.y;
    if (blockIdx.y == 0 && ty == 0) {
        const float* bsrc = (z == 0) ? bq : (z == 1) ? bk : bv;
        bqkv[z * Dd + n0 + tx] = bsrc[n0 + tx];
    }
    #pragma unroll
    for (int dy = 0; dy < 32; dy += 8)
        tile[ty + dy][tx] = W[(size_t)(k0 + ty + dy) * Dd + n0 + tx];
    __syncthreads();
    #pragma unroll
    for (int dy = 0; dy < 32; dy += 8) {
        const size_t o = woff + (size_t)(n0 + ty + dy) * Dd + k0 + tx;
        T[o] = __float2half_rn(tile[tx][ty + dy]);
    }
}

// ============ fp32 -> fp16 elementwise ============
__global__ void to_f16_kernel(const float* __restrict__ in, __half* __restrict__ out)
{
    const int i = blockIdx.x * 256 + threadIdx.x;
    float4 v = ((const float4*)in)[i];
    ((uint32_t*)out)[i * 2 + 0] = packh2(v.x, v.y);
    ((uint32_t*)out)[i * 2 + 1] = packh2(v.z, v.w);
}

// ============ V fp16 row-major -> V^T fp16 [b,ch,tok] ============
__global__ void vT16_kernel(const __half* __restrict__ v16,
                            __half* __restrict__ vt16)
{
    __shared__ __half tile[32][40];
    const int tok0 = blockIdx.x * 32, ch0 = blockIdx.y * 32, b = blockIdx.z;
    const int tx = threadIdx.x, ty = threadIdx.y;
    #pragma unroll
    for (int dy = 0; dy < 32; dy += 8)
        tile[ty + dy][tx] = v16[((size_t)(b * Nn + tok0 + ty + dy)) * Dd + ch0 + tx];
    __syncthreads();
    #pragma unroll
    for (int dy = 0; dy < 32; dy += 8) {
        const size_t o = ((size_t)(b * Dd + ch0 + ty + dy)) * Nn + tok0 + tx;
        vt16[o] = tile[tx][ty + dy];
    }
}

// ============ RPE: tf32 layer1 -> relu -> fp16 layer2 (tensor) ============
__global__ __launch_bounds__(256)
void rpe_kernel(const float* __restrict__ rel_pos,
                const float* __restrict__ R1, const float* __restrict__ rb1,
                const float* __restrict__ R2, const float* __restrict__ rb2,
                __half* __restrict__ rpe)
{
    __shared__ __half sh_out[8][128];

    const int j0 = blockIdx.x * 128;
    const int i  = blockIdx.y;
    const int b  = blockIdx.z;
    const int t  = threadIdx.x;
    const int w = t >> 5, lane = t & 31;
    const int gid = lane >> 2, tig = lane & 3;
    const int jw = w * 16;

    uint32_t b1f[8];
    #pragma unroll
    for (int ut = 0; ut < 8; ut++) b1f[ut] = f2tf(R1[tig * 64 + ut * 8 + gid]);

    const float* rp = rel_pos + ((size_t)(b * Nn + i) * Nn + j0 + jw) * 4;
    uint32_t a1f[4];
    a1f[0] = f2tf(rp[gid * 4 + tig]);
    a1f[1] = f2tf(rp[(gid + 8) * 4 + tig]);
    a1f[2] = 0u;
    a1f[3] = 0u;

    float c1[8][4];
    #pragma unroll
    for (int ut = 0; ut < 8; ut++) {
        c1[ut][0] = 0.f; c1[ut][1] = 0.f; c1[ut][2] = 0.f; c1[ut][3] = 0.f;
        uint32_t bb[2] = { b1f[ut], 0u };
        mma1688tf(c1[ut], a1f, bb);
        const float r0 = rb1[ut * 8 + 2 * tig], r1 = rb1[ut * 8 + 2 * tig + 1];
        c1[ut][0] = fmaxf(c1[ut][0] + r0, 0.f);
        c1[ut][1] = fmaxf(c1[ut][1] + r1, 0.f);
        c1[ut][2] = fmaxf(c1[ut][2] + r0, 0.f);
        c1[ut][3] = fmaxf(c1[ut][3] + r1, 0.f);
    }

    float c2[4] = {0.f, 0.f, 0.f, 0.f};
    #pragma unroll
    for (int ks = 0; ks < 4; ks++) {
        uint32_t a2[4];
        a2[0] = packh2(c1[2 * ks][0],     c1[2 * ks][1]);
        a2[1] = packh2(c1[2 * ks][2],     c1[2 * ks][3]);
        a2[2] = packh2(c1[2 * ks + 1][0], c1[2 * ks + 1][1]);
        a2[3] = packh2(c1[2 * ks + 1][2], c1[2 * ks + 1][3]);
        uint32_t b2[2];
        b2[0] = packh2(R2[(16 * ks + 2 * tig) * 8 + gid],     R2[(16 * ks + 2 * tig + 1) * 8 + gid]);
        b2[1] = packh2(R2[(16 * ks + 8 + 2 * tig) * 8 + gid], R2[(16 * ks + 9 + 2 * tig) * 8 + gid]);
        mma16816h(c2, a2, b2);
    }
    const float rbA = rb2[2 * tig], rbB = rb2[2 * tig + 1];
    sh_out[2 * tig    ][jw + gid]     = __float2half(c2[0] + rbA);
    sh_out[2 * tig + 1][jw + gid]     = __float2half(c2[1] + rbB);
    sh_out[2 * tig    ][jw + gid + 8] = __float2half(c2[2] + rbA);
    sh_out[2 * tig + 1][jw + gid + 8] = __float2half(c2[3] + rbB);
    __syncthreads();

    const uint32_t* src = (const uint32_t*)sh_out;
    #pragma unroll
    for (int u = t; u < 512; u += 256) {
        const int hh = u >> 6, col = u & 63;
        ((uint32_t*)(rpe + (((size_t)(b * Hh + hh) * Nn + i) * Nn + j0)))[col] = src[hh * 64 + col];
    }
}

// ============ attention: R13 shape + ldmatrix K/V frags, fp16 partials ============
__global__ __launch_bounds__(128)
void attn_mma_kernel(const __half* __restrict__ q16,
                     const __half* __restrict__ k16,
                     const __half* __restrict__ vt16,
                     const __half* __restrict__ rpe,
                     __half* __restrict__ pacc16, float* __restrict__ pm, float* __restrict__ pl)
{
    __shared__ __half sK[2][64 * 72];
    __shared__ __half sV[2][64 * 72];

    const int it = blockIdx.x;
    const int b  = blockIdx.y;
    const int h  = blockIdx.z >> 1;
    const int sp = blockIdx.z & 1;
    const int t = threadIdx.x;
    const int w = t >> 5, lane = t & 31;
    const int gid = lane >> 2, tig = lane & 3;
    const int i0 = it * 64 + w * 16;
    const int jbeg = sp * NSPLIT;
    const int njt = NSPLIT / 64;

    const int g4    = lane >> 3;
    const int b_row = ((g4 >> 1) << 3) + (lane & 7);
    const int b_kh  = (g4 & 1) << 3;

    uint32_t aq[4][4];
    {
        const __half* qb = q16 + (size_t)(b * Nn) * Dd + h * 64;
        #pragma unroll
        for (int ks = 0; ks < 4; ks++) {
            const int kb = ks * 16 + 2 * tig;
            const __half* p0 = qb + (size_t)(i0 + gid) * Dd + kb;
            const __half* p1 = qb + (size_t)(i0 + gid + 8) * Dd + kb;
            aq[ks][0] = *(const uint32_t*)p0;
            aq[ks][1] = *(const uint32_t*)p1;
            aq[ks][2] = *(const uint32_t*)(p0 + 8);
            aq[ks][3] = *(const uint32_t*)(p1 + 8);
        }
    }

    float acc[8][4];
    #pragma unroll
    for (int nf = 0; nf < 8; nf++)
        #pragma unroll
        for (int r = 0; r < 4; r++) acc[nf][r] = 0.0f;
    float m0 = -1e30f, m1 = -1e30f, l0 = 0.0f, l1 = 0.0f;

    auto stage_tile = [&](int st, int j0) {
        #pragma unroll
        for (int u = t; u < 512; u += 128) {
            const int r = u >> 3, c8 = (u & 7) << 3;
            cp16(smem_u32(&sK[st][r * 72 + c8]),
                 k16 + (size_t)(b * Nn + j0 + r) * Dd + h * 64 + c8);
        }
        #pragma unroll
        for (int u = t; u < 512; u += 128) {
            const int r = u >> 3, c8 = (u & 7) << 3;
            cp16(smem_u32(&sV[st][r * 72 + c8]),
                 vt16 + (size_t)(b * Dd + h * 64 + r) * Nn + j0 + c8);
        }
        cp_commit();
    };

    stage_tile(0, jbeg);

    for (int jt = 0; jt < njt; jt++) {
        const int j0 = jbeg + jt * 64;
        cp_wait0();
        __syncthreads();
        if (jt + 1 < njt) stage_tile((jt + 1) & 1, j0 + 64);

        const __half* sKt = sK[jt & 1];
        const __half* sVt = sV[jt & 1];

        float s[8][4];
        #pragma unroll
        for (int p = 0; p < 4; p++) {
            float* sE = s[2 * p];
            float* sO = s[2 * p + 1];
            sE[0] = 0.f; sE[1] = 0.f; sE[2] = 0.f; sE[3] = 0.f;
            sO[0] = 0.f; sO[1] = 0.f; sO[2] = 0.f; sO[3] = 0.f;
            #pragma unroll
            for (int ks = 0; ks < 4; ks++) {
                uint32_t r0, r1, r2, r3;
                ldsm_x4(r0, r1, r2, r3,
                        smem_u32(sKt + (p * 16 + b_row) * 72 + ks * 16 + b_kh));
                uint32_t bA[2] = { r0, r1 }, bB[2] = { r2, r3 };
                mma16816h(sE, aq[ks], bA);
                mma16816h(sO, aq[ks], bB);
            }
        }
        {
            const uint32_t* rp32 = (const uint32_t*)rpe;
            const size_t row0 = ((size_t)(b * Hh + h) * Nn + i0 + gid) * 512 + (j0 >> 1) + tig;
            const size_t row1 = row0 + 8 * 512;
            #pragma unroll
            for (int jf = 0; jf < 8; jf++) {
                uint32_t u0 = rp32[row0 + jf * 4];
                uint32_t u1 = rp32[row1 + jf * 4];
                float2 f0 = __half22float2(*(const __half2*)&u0);
                float2 f1 = __half22float2(*(const __half2*)&u1);
                s[jf][0] += f0.x; s[jf][1] += f0.y;
                s[jf][2] += f1.x; s[jf][3] += f1.y;
            }
        }

        float mx0 = -1e30f, mx1 = -1e30f;
        #pragma unroll
        for (int jf = 0; jf < 8; jf++) {
            mx0 = fmaxf(mx0, fmaxf(s[jf][0], s[jf][1]));
            mx1 = fmaxf(mx1, fmaxf(s[jf][2], s[jf][3]));
        }
        mx0 = fmaxf(mx0, __shfl_xor_sync(0xffffffffu, mx0, 1));
        mx0 = fmaxf(mx0, __shfl_xor_sync(0xffffffffu, mx0, 2));
        mx1 = fmaxf(mx1, __shfl_xor_sync(0xffffffffu, mx1, 1));
        mx1 = fmaxf(mx1, __shfl_xor_sync(0xffffffffu, mx1, 2));
        const float M0 = fmaxf(m0, mx0), M1 = fmaxf(m1, mx1);
        const float sc0 = __expf(m0 - M0), sc1 = __expf(m1 - M1);
        float ls0 = 0.0f, ls1 = 0.0f;
        #pragma unroll
        for (int jf = 0; jf < 8; jf++) {
            s[jf][0] = __expf(s[jf][0] - M0); ls0 += s[jf][0];
            s[jf][1] = __expf(s[jf][1] - M0); ls0 += s[jf][1];
            s[jf][2] = __expf(s[jf][2] - M1); ls1 += s[jf][2];
            s[jf][3] = __expf(s[jf][3] - M1); ls1 += s[jf][3];
        }
        ls0 += __shfl_xor_sync(0xffffffffu, ls0, 1);
        ls0 += __shfl_xor_sync(0xffffffffu, ls0, 2);
        ls1 += __shfl_xor_sync(0xffffffffu, ls1, 1);
        ls1 += __shfl_xor_sync(0xffffffffu, ls1, 2);
        l0 = l0 * sc0 + ls0;
        l1 = l1 * sc1 + ls1;
        m0 = M0; m1 = M1;
        #pragma unroll
        for (int nf = 0; nf < 8; nf++) {
            acc[nf][0] *= sc0; acc[nf][1] *= sc0;
            acc[nf][2] *= sc1; acc[nf][3] *= sc1;
        }

        uint32_t ph[4][4];
        #pragma unroll
        for (int kf = 0; kf < 4; kf++) {
            const int jE = 2 * kf, jO = 2 * kf + 1;
            ph[kf][0] = packh2(s[jE][0], s[jE][1]);
            ph[kf][1] = packh2(s[jE][2], s[jE][3]);
            ph[kf][2] = packh2(s[jO][0], s[jO][1]);
            ph[kf][3] = packh2(s[jO][2], s[jO][3]);
        }

        #pragma unroll
        for (int p = 0; p < 4; p++) {
            float* aE = acc[2 * p];
            float* aO = acc[2 * p + 1];
            #pragma unroll
            for (int kf = 0; kf < 4; kf++) {
                uint32_t r0, r1, r2, r3;
                ldsm_x4(r0, r1, r2, r3,
                        smem_u32(sVt + (p * 16 + b_row) * 72 + kf * 16 + b_kh));
                uint32_t bA[2] = { r0, r1 }, bB[2] = { r2, r3 };
                mma16816h(aE, ph[kf], bA);
                mma16816h(aO, ph[kf], bB);
            }
        }
        __syncthreads();
    }

    __half* pab = pacc16 + (size_t)sp * (Bb * Nn * Dd) + (size_t)b * (Nn * Dd);
    #pragma unroll
    for (int nf = 0; nf < 8; nf++) {
        const int ch = h * 64 + nf * 8 + 2 * tig;
        *(uint32_t*)&pab[(size_t)(i0 + gid) * Dd + ch]     = packh2(acc[nf][0], acc[nf][1]);
        *(uint32_t*)&pab[(size_t)(i0 + gid + 8) * Dd + ch] = packh2(acc[nf][2], acc[nf][3]);
    }
    if (tig == 0) {
        const size_t ix0 = (((size_t)sp * Bb + b) * Nn + i0 + gid) * Hh + h;
        const size_t ix1 = (((size_t)sp * Bb + b) * Nn + i0 + gid + 8) * Hh + h;
        pm[ix0] = m0; pl[ix0] = l0;
        pm[ix1] = m1; pl[ix1] = l1;
    }
}

// ---------------- combine fp16 partials -> ao fp16 ----------------
__global__ void attn_combine_kernel(const __half* __restrict__ pacc16,
                                    const float* __restrict__ pm,
                                    const float* __restrict__ pl,
                                    __half* __restrict__ ao16)
{
    const int i = blockIdx.x;
    const int b = blockIdx.y;
    const int t = threadIdx.x;
    __shared__ float sh_w[SPL][Hh];
    __shared__ float sh_invL[Hh];

    if (t < Hh) {
        float m[SPL], l[SPL];
        float M = -1e30f;
        #pragma unroll
        for (int s = 0; s < SPL; s++) {
            size_t idx = (((size_t)s * Bb + b) * Nn + i) * Hh + t;
            m[s] = pm[idx]; l[s] = pl[idx];
            M = fmaxf(M, m[s]);
        }
        float L = 0.0f;
        #pragma unroll
        for (int s = 0; s < SPL; s++) {
            float w = __expf(m[s] - M);
            sh_w[s][t] = w;
            L = fmaf(l[s], w, L);
        }
        sh_invL[t] = 1.0f / L;
    }
    __syncthreads();

    const int e0 = t, e1 = t + 256;
    const int he0 = t >> 6, he1 = he0 + 4;
    const size_t row = ((size_t)(b * Nn) + i) * Dd;
    float a0 = 0.0f, a1 = 0.0f;
    #pragma unroll
    for (int s = 0; s < SPL; s++) {
        const __half* pab = pacc16 + (size_t)s * (Bb * Nn * Dd);
        a0 = fmaf(__half2float(pab[row + e0]), sh_w[s][he0], a0);
        a1 = fmaf(__half2float(pab[row + e1]), sh_w[s][he1], a1);
    }
    ao16[row + e0] = __float2half(a0 * sh_invL[he0]);
    ao16[row + e1] = __float2half(a1 * sh_invL[he1]);
}

// ---------------- residual + LayerNorm ----------------
template<int H16>
__global__ void ln_kernel(const float* __restrict__ x, const float* __restrict__ add,
                          const float* __restrict__ g, const float* __restrict__ bet,
                          float* __restrict__ out, __half* __restrict__ outH)
{
    const int row = blockIdx.x;
    const int t = threadIdx.x;
    const size_t base = (size_t)row * Dd;
    float v0 = x[base + t]       + add[base + t];
    float v1 = x[base + t + 256] + add[base + t + 256];
    float s  = v0 + v1;
    float s2 = v0 * v0 + v1 * v1;
    #pragma unroll
    for (int o = 16; o > 0; o >>= 1) {
        s  += __shfl_xor_sync(0xffffffffu, s,  o);
        s2 += __shfl_xor_sync(0xffffffffu, s2, o);
    }
    __shared__ float ws[8], ws2[8];
    __shared__ float mu_s, rs_s;
    if ((t & 31) == 0) { ws[t >> 5] = s; ws2[t >> 5] = s2; }
    __syncthreads();
    if (t == 0) {
        float S = 0.0f, S2 = 0.0f;
        #pragma unroll
        for (int w = 0; w < 8; w++) { S += ws[w]; S2 += ws2[w]; }
        float mu = S * (1.0f / 512.0f);
        float var = S2 * (1.0f / 512.0f) - mu * mu;
        mu_s = mu;
        rs_s = rsqrtf(var + 1e-5f);
    }
    __syncthreads();
    float o0 = (v0 - mu_s) * rs_s * g[t]       + bet[t];
    float o1 = (v1 - mu_s) * rs_s * g[t + 256] + bet[t + 256];
    out[base + t]       = o0;
    out[base + t + 256] = o1;
    if (H16) {
        outH[base + t]       = __float2half(o0);
        outH[base + t + 256] = __float2half(o1);
    }
}

// ---------------- launch ----------------
extern "C" void kernel_launch(void* const* d_in, const int* in_sizes, int n_in,
                              void* d_out, int out_size)
{
    (void)in_sizes; (void)n_in; (void)out_size;
    const float* x       = (const float*)d_in[0];
    const float* rel_pos = (const float*)d_in[1];
    const float* Wq = (const float*)d_in[2];  const float* bq = (const float*)d_in[3];
    const float* Wk = (const float*)d_in[4];  const float* bk = (const float*)d_in[5];
    const float* Wv = (const float*)d_in[6];  const float* bv = (const float*)d_in[7];
    const float* Wo = (const float*)d_in[8];  const float* bo = (const float*)d_in[9];
    const float* R1 = (const float*)d_in[10]; const float* rb1 = (const float*)d_in[11];
    const float* R2 = (const float*)d_in[12]; const float* rb2 = (const float*)d_in[13];
    const float* g1 = (const float*)d_in[14]; const float* b1 = (const float*)d_in[15];
    const float* g2 = (const float*)d_in[16]; const float* b2 = (const float*)d_in[17];
    const float* F1 = (const float*)d_in[18]; const float* fb1 = (const float*)d_in[19];
    const float* F2 = (const float*)d_in[20]; const float* fb2 = (const float*)d_in[21];
    float* outp = (float*)d_out;

    float *wo, *x1, *f2, *pm, *pl, *bqkv;
    __half *pacc16;
    cudaGetSymbolAddress((void**)&wo,   g_wo);
    cudaGetSymbolAddress((void**)&x1,   g_x1);
    cudaGetSymbolAddress((void**)&f2,   g_f2);
    cudaGetSymbolAddress((void**)&pacc16, g_pacc16);
    cudaGetSymbolAddress((void**)&pm,   g_pm);
    cudaGetSymbolAddress((void**)&pl,   g_pl);
    cudaGetSymbolAddress((void**)&bqkv, g_bqkv);

    __half *x16, *q16, *k16, *v16, *vt16, *ao16, *x116, *h16;
    __half *wqkvt16, *woth16, *f1th16, *f2th16, *rpe;
    cudaGetSymbolAddress((void**)&x16,  g_x16);
    cudaGetSymbolAddress((void**)&q16,  g_q16);
    cudaGetSymbolAddress((void**)&k16,  g_k16);
    cudaGetSymbolAddress((void**)&v16,  g_v16);
    cudaGetSymbolAddress((void**)&vt16, g_vt16);
    cudaGetSymbolAddress((void**)&ao16, g_ao16);
    cudaGetSymbolAddress((void**)&x116, g_x116);
    cudaGetSymbolAddress((void**)&h16,  g_h16);
    cudaGetSymbolAddress((void**)&wqkvt16, g_wqkvt16);
    cudaGetSymbolAddress((void**)&woth16, g_woth16);
    cudaGetSymbolAddress((void**)&f1th16, g_f1th16);
    cudaGetSymbolAddress((void**)&f2th16, g_f2th16);
    cudaGetSymbolAddress((void**)&rpe,  g_rpe);

    const int M = Bb * Nn;
    dim3 tb(32, 8);

    constexpr int AS = 40;
    const int SMEM_64   = (2 * 64 * AS + 2 * 64 * AS) * (int)sizeof(__half);    // 20480
    const int SMEM_F128 = (2 * 128 * AS + 2 * 128 * AS) * (int)sizeof(__half);  // 40960
    cudaFuncSetAttribute(gemm_f16_kernel<64,64,0>,   cudaFuncAttributeMaxDynamicSharedMemorySize, SMEM_64);
    cudaFuncSetAttribute(gemm_f16_kernel<128,128,2>, cudaFuncAttributeMaxDynamicSharedMemorySize, SMEM_F128);
    cudaFuncSetAttribute(gemm_f16_kernel<128,128,3>, cudaFuncAttributeMaxDynamicSharedMemorySize, SMEM_F128);

    // ---- fork: side stream: QKV weight transpose first, then rpe + Wo/FFN transposes
    cudaEventRecord(g_ss.fork, 0);
    cudaStreamWaitEvent(g_ss.s, g_ss.fork, 0);
    transpose_f16_qkv_kernel<<<dim3(16, 16, 3), tb, 0, g_ss.s>>>(Wq, Wk, Wv, bq, bk, bv, wqkvt16, bqkv);
    cudaEventRecord(g_ss.wq, g_ss.s);
    rpe_kernel<<<dim3(Nn / 128, Nn, Bb), 256, 0, g_ss.s>>>(rel_pos, R1, rb1, R2, rb2, rpe);
    transpose_f16_kernel<<<dim3(16, 16), tb, 0, g_ss.s>>>(Wo, woth16, Dd, Dd);
    transpose_f16_kernel<<<dim3(64, 16), tb, 0, g_ss.s>>>(F1, f1th16, Dd, FFN);
    transpose_f16_kernel<<<dim3(16, 64), tb, 0, g_ss.s>>>(F2, f2th16, FFN, Dd);
    cudaEventRecord(g_ss.join, g_ss.s);

    // ---- main stream ----
    to_f16_kernel<<<(M * Dd / 4) / 256, 256>>>(x, x16);
    cudaStreamWaitEvent(0, g_ss.wq, 0);

    gemm_f16_kernel<128,128,3><<<dim3(3 * Dd / 128, M / 128), 256, SMEM_F128>>>(
        x16, wqkvt16, bqkv, nullptr, q16, k16, v16, M, Dd, 3 * Dd);
    vT16_kernel<<<dim3(Nn / 32, Dd / 32, Bb), tb>>>(v16, vt16);

    cudaStreamWaitEvent(0, g_ss.join, 0);

    attn_mma_kernel<<<dim3(Nn / 64, Bb, Hh * SPL), 128>>>(q16, k16, vt16, rpe, pacc16, pm, pl);
    attn_combine_kernel<<<dim3(Nn, Bb), 256>>>(pacc16, pm, pl, ao16);

    gemm_f16_kernel<64,64,0><<<dim3(Dd / 64, M / 64), 256, SMEM_64>>>(
        ao16, woth16, bo, wo, nullptr, nullptr, nullptr, M, Dd, Dd);
    ln_kernel<1><<<M, 256>>>(x, wo, g1, b1, x1, x116);

    gemm_f16_kernel<128,128,2><<<dim3(FFN / 128, M / 128), 256, SMEM_F128>>>(
        x116, f1th16, fb1, nullptr, h16, nullptr, nullptr, M, Dd, FFN);
    gemm_f16_kernel<64,64,0><<<dim3(Dd / 64, M / 64), 256, SMEM_64>>>(
        h16, f2th16, fb2, f2, nullptr, nullptr, nullptr, M, FFN, Dd);
    ln_kernel<0><<<M, 256>>>(x1, f2, g2, b2, outp, nullptr);
}